// round 5
// baseline (speedup 1.0000x reference)
#include <cuda_runtime.h>
#include <cuda_bf16.h>
#include <cstdint>

// ---------------------------------------------------------------------------
// Problem constants
// ---------------------------------------------------------------------------
#define BSZ   8
#define TLEN  4096
#define HDIM  1024
#define N3H   3072
#define KSZ   1024
#define MROWS (BSZ * TLEN)      // 32768
#define NC    32                // scan chunks per sequence
#define CL    (TLEN / NC)       // 128 steps per chunk

// int8 fixed-point scales
#define SA_SCALE 15.875f                 // 127/8   (|a| <= 8 guaranteed)
#define SW_SCALE 508.0f                  // 127/0.25 (|w| <= 0.25 guaranteed)
#define INV_SCALE (1.0f / (SA_SCALE * SW_SCALE))

// ---------------------------------------------------------------------------
// Device scratch (no allocations allowed)
// ---------------------------------------------------------------------------
__device__ float  g_z [(size_t)MROWS * N3H];      // GEMM output z
__device__ float  g_h [(size_t)MROWS * HDIM];     // inter-layer h
__device__ int8_t g_a1[(size_t)MROWS * KSZ];      // A digit 1
__device__ int8_t g_a2[(size_t)MROWS * KSZ];      // A digit 2
__device__ int8_t g_w1[(size_t)N3H * KSZ];        // W^T digit 1 [N,K]
__device__ int8_t g_w2[(size_t)N3H * KSZ];        // W^T digit 2 [N,K]
__device__ float  g_cP[(size_t)BSZ * NC * HDIM];  // chunk coeff product
__device__ float  g_cS[(size_t)BSZ * NC * HDIM];  // chunk local scan end
__device__ float  g_pf[(size_t)BSZ * NC * HDIM];  // chunk carry-in

// ---------------------------------------------------------------------------
// Helpers
// ---------------------------------------------------------------------------
__device__ __forceinline__ uint32_t smem_u32(const void* p) {
    uint32_t a;
    asm("{ .reg .u64 t; cvta.to.shared.u64 t, %1; cvt.u32.u64 %0, t; }"
        : "=r"(a) : "l"(p));
    return a;
}

__device__ __forceinline__ void cp16(uint32_t dst, const void* src) {
    asm volatile("cp.async.cg.shared.global [%0], [%1], 16;" :: "r"(dst), "l"(src));
}

__device__ __forceinline__ void ldsm4(uint32_t r[4], uint32_t addr) {
    asm volatile("ldmatrix.sync.aligned.m8n8.x4.shared.b16 {%0,%1,%2,%3}, [%4];"
        : "=r"(r[0]), "=r"(r[1]), "=r"(r[2]), "=r"(r[3]) : "r"(addr));
}

__device__ __forceinline__ void imma(int c[4], const uint32_t a[4],
                                     uint32_t b0, uint32_t b1) {
    asm volatile(
        "mma.sync.aligned.m16n8k32.row.col.s32.s8.s8.s32 "
        "{%0,%1,%2,%3}, {%4,%5,%6,%7}, {%8,%9}, {%0,%1,%2,%3};"
        : "+r"(c[0]), "+r"(c[1]), "+r"(c[2]), "+r"(c[3])
        : "r"(a[0]), "r"(a[1]), "r"(a[2]), "r"(a[3]), "r"(b0), "r"(b1));
}

__device__ __forceinline__ float fsig(float x) {        // sigmoid(x)
    return __fdividef(1.0f, 1.0f + __expf(-x));
}

// quantize one fp32 value into two s8 digits (val*S ~= d1 + d2/128)
__device__ __forceinline__ void quant2(float v, float S, int8_t& d1, int8_t& d2) {
    float q = v * S;
    int i1 = __float2int_rn(q);
    i1 = max(-127, min(127, i1));
    int i2 = __float2int_rn((q - (float)i1) * 128.0f);
    i2 = max(-127, min(127, i2));
    d1 = (int8_t)i1;
    d2 = (int8_t)i2;
}

// ---------------------------------------------------------------------------
// GEMM: C[M,3H] = A[M,K] * W[K,3H] via int8 digits:
//   z = (A1*W1 + (A1*W2 + A2*W1)/128) / (SA*SW)
// B passed transposed ([N,K] K-major, s8).
// Tile 128x128, BK=32 (bytes), 4-stage cp.async pipe, 8 warps x (64x32).
// ---------------------------------------------------------------------------
#define GM_BM 128
#define GM_BN 128
#define GM_BK 32
#define STAGES 4
#define KITERS (KSZ / GM_BK)            // 32
#define OPB 4096                        // operand tile: 128 rows x 32 B
#define STB (4 * OPB)                   // stage: A1,A2,B1,B2 = 16 KB
#define SMEM_DYN (STAGES * STB)         // 64 KB

__device__ __forceinline__ void load_stage(
    uint32_t sbase, int stage,
    const int8_t* __restrict__ A1, const int8_t* __restrict__ A2,
    const int8_t* __restrict__ B1, const int8_t* __restrict__ B2,
    int bm, int bn, int kt, int tid)
{
    const int k0 = kt * GM_BK;
    const uint32_t st = sbase + (uint32_t)stage * STB;
    #pragma unroll
    for (int i = 0; i < 4; ++i) {
        const int idx = tid + i * 256;          // 0 .. 1023
        const int op = idx >> 8;                // 0=A1 1=A2 2=B1 3=B2
        const int j = idx & 255;
        const int r = j >> 1, g = j & 1;
        const int8_t* base = (op == 0) ? A1 : (op == 1) ? A2 : (op == 2) ? B1 : B2;
        const int grow = ((op < 2) ? bm : bn) + r;
        const void* src = base + (size_t)grow * KSZ + k0 + g * 16;
        const uint32_t dst = st + (uint32_t)op * OPB + r * 32
                           + ((g ^ ((r >> 2) & 1)) << 4);
        cp16(dst, src);
    }
    asm volatile("cp.async.commit_group;" ::: "memory");
}

__global__ void __launch_bounds__(256, 1)
gemm_imma(const int8_t* __restrict__ A1, const int8_t* __restrict__ A2,
          const int8_t* __restrict__ B1, const int8_t* __restrict__ B2,
          float* __restrict__ C)
{
    extern __shared__ char dsm[];
    const uint32_t sbase = smem_u32(dsm);

    const int tid  = threadIdx.x;
    const int lane = tid & 31;
    const int wid  = tid >> 5;
    const int wm   = wid >> 2;                 // 0..1  (64-row slab)
    const int wn   = wid & 3;                  // 0..3  (32-col slab)
    const int bm   = blockIdx.y * GM_BM;
    const int bn   = blockIdx.x * GM_BN;

    // ldmatrix lane addressing (b16 view: 16 b16 = 32 s8 per row)
    const int rowA = lane & 15;
    const int gA   = lane >> 4;
    const uint32_t aoff = (uint32_t)rowA * 32 + ((gA ^ ((rowA >> 2) & 1)) << 4);
    const int rowB = (lane & 7) + (lane >> 4) * 8;
    const int gB   = (lane >> 3) & 1;
    const uint32_t boff = (uint32_t)rowB * 32 + ((gB ^ ((rowB >> 2) & 1)) << 4);

    int acc_hi[4][4][4], acc_mid[4][4][4];
    #pragma unroll
    for (int i = 0; i < 4; ++i)
        #pragma unroll
        for (int j = 0; j < 4; ++j)
            #pragma unroll
            for (int q = 0; q < 4; ++q) { acc_hi[i][j][q] = 0; acc_mid[i][j][q] = 0; }

    #pragma unroll
    for (int s = 0; s < STAGES - 1; ++s)
        load_stage(sbase, s, A1, A2, B1, B2, bm, bn, s, tid);

    for (int kt = 0; kt < KITERS; ++kt) {
        asm volatile("cp.async.wait_group %0;" :: "n"(STAGES - 2) : "memory");
        __syncthreads();

        if (kt + STAGES - 1 < KITERS)
            load_stage(sbase, (kt + STAGES - 1) & (STAGES - 1),
                       A1, A2, B1, B2, bm, bn, kt + STAGES - 1, tid);

        const uint32_t st = sbase + (uint32_t)(kt & (STAGES - 1)) * STB;

        uint32_t a1f[4][4], a2f[4][4];
        #pragma unroll
        for (int mf = 0; mf < 4; ++mf) {
            const uint32_t ao = st + (uint32_t)(wm * 64 + mf * 16) * 32 + aoff;
            ldsm4(a1f[mf], ao);
            ldsm4(a2f[mf], ao + OPB);
        }
        #pragma unroll
        for (int n16 = 0; n16 < 2; ++n16) {
            uint32_t b1f[4], b2f[4];
            const uint32_t bo = st + 2 * OPB
                              + (uint32_t)(wn * 32 + n16 * 16) * 32 + boff;
            ldsm4(b1f, bo);
            ldsm4(b2f, bo + OPB);
            #pragma unroll
            for (int mf = 0; mf < 4; ++mf)
                #pragma unroll
                for (int h = 0; h < 2; ++h) {
                    imma(acc_hi [mf][n16 * 2 + h], a1f[mf], b1f[2 * h], b1f[2 * h + 1]);
                    imma(acc_mid[mf][n16 * 2 + h], a1f[mf], b2f[2 * h], b2f[2 * h + 1]);
                    imma(acc_mid[mf][n16 * 2 + h], a2f[mf], b1f[2 * h], b1f[2 * h + 1]);
                }
        }
    }

    // epilogue: dequantize and store fp32
    #pragma unroll
    for (int mf = 0; mf < 4; ++mf) {
        const int row = bm + wm * 64 + mf * 16 + (lane >> 2);
        #pragma unroll
        for (int nf = 0; nf < 4; ++nf) {
            const int* hi = acc_hi[mf][nf];
            const int* mi = acc_mid[mf][nf];
            const int col = bn + wn * 32 + (nf >> 1) * 16 + (nf & 1) * 8 + (lane & 3) * 2;
            float z0 = fmaf((float)mi[0], 0.0078125f, (float)hi[0]) * INV_SCALE;
            float z1 = fmaf((float)mi[1], 0.0078125f, (float)hi[1]) * INV_SCALE;
            float z2 = fmaf((float)mi[2], 0.0078125f, (float)hi[2]) * INV_SCALE;
            float z3 = fmaf((float)mi[3], 0.0078125f, (float)hi[3]) * INV_SCALE;
            *(float2*)(C + (size_t)row * N3H + col)       = make_float2(z0, z1);
            *(float2*)(C + (size_t)(row + 8) * N3H + col) = make_float2(z2, z3);
        }
    }
}

// ---------------------------------------------------------------------------
// quantize dense fp32 A -> two s8 digit arrays
// ---------------------------------------------------------------------------
__global__ void __launch_bounds__(256)
quant_a_kernel(const float* __restrict__ x, int8_t* __restrict__ d1,
               int8_t* __restrict__ d2)
{
    const size_t i = (size_t)blockIdx.x * blockDim.x + threadIdx.x;
    float4 v = ((const float4*)x)[i];
    char4 c1, c2;
    quant2(v.x, SA_SCALE, (int8_t&)c1.x, (int8_t&)c2.x);
    quant2(v.y, SA_SCALE, (int8_t&)c1.y, (int8_t&)c2.y);
    quant2(v.z, SA_SCALE, (int8_t&)c1.z, (int8_t&)c2.z);
    quant2(v.w, SA_SCALE, (int8_t&)c1.w, (int8_t&)c2.w);
    ((char4*)d1)[i] = c1;
    ((char4*)d2)[i] = c2;
}

// ---------------------------------------------------------------------------
// transpose + quantize W: W[K,3H] -> Wt digits [3H,K]
// ---------------------------------------------------------------------------
__global__ void __launch_bounds__(256)
quant_wt_kernel(const float* __restrict__ W, int8_t* __restrict__ d1,
                int8_t* __restrict__ d2)
{
    __shared__ float tile[32][33];
    const int n0 = blockIdx.x * 32;
    const int k0 = blockIdx.y * 32;
    const int tx = threadIdx.x, ty = threadIdx.y;   // 32 x 8
    #pragma unroll
    for (int r = ty; r < 32; r += 8)
        tile[r][tx] = W[(size_t)(k0 + r) * N3H + n0 + tx];
    __syncthreads();
    #pragma unroll
    for (int r = ty; r < 32; r += 8) {
        float v = tile[tx][r];                      // = W[k0+tx][n0+r]
        int8_t q1, q2;
        quant2(v, SW_SCALE, q1, q2);
        size_t o = (size_t)(n0 + r) * KSZ + k0 + tx;
        d1[o] = q1;
        d2[o] = q2;
    }
}

// ---------------------------------------------------------------------------
// Scan phase 1: per (b, chunk, c): P = prod coeff, S = chunk-local scan end
// ---------------------------------------------------------------------------
__global__ void __launch_bounds__(256)
scan_p1(const float* __restrict__ z, float* __restrict__ cP, float* __restrict__ cS)
{
    const int idx = blockIdx.x * blockDim.x + threadIdx.x;   // B*NC*H
    const int c = idx & (HDIM - 1);
    const int chunk = (idx >> 10) & (NC - 1);
    const int b = idx >> 15;
    const float* zb = z + ((size_t)b * TLEN + (size_t)chunk * CL) * N3H + c;
    float P = 1.0f, S = 0.0f;
    #pragma unroll 8
    for (int t = 0; t < CL; ++t) {
        float zh = __ldcs(zb + (size_t)t * N3H);
        float zg = __ldcs(zb + (size_t)t * N3H + HDIM);
        float e  = __expf(zg);
        float cf = __fdividef(1.0f, 1.0f + e);       // sigmoid(-zg)
        float sg = 1.0f - cf;                        // sigmoid(zg)
        float gv = (zh >= 0.0f) ? (zh + 0.5f) : fsig(zh);
        S = fmaf(cf, S, sg * gv);
        P *= cf;
    }
    cP[idx] = P;
    cS[idx] = S;
}

// ---------------------------------------------------------------------------
// Scan phase 2: sequential combine over chunks -> carry-in per chunk
// ---------------------------------------------------------------------------
__global__ void __launch_bounds__(256)
scan_p2(const float* __restrict__ cP, const float* __restrict__ cS, float* __restrict__ pf)
{
    const int idx = blockIdx.x * blockDim.x + threadIdx.x;   // B*H
    const int c = idx & (HDIM - 1);
    const int b = idx >> 10;
    float s = 0.0f;
    #pragma unroll
    for (int j = 0; j < NC; ++j) {
        size_t o = ((size_t)(b * NC + j) << 10) + c;
        pf[o] = s;
        s = fmaf(cP[o], s, cS[o]);
    }
}

// ---------------------------------------------------------------------------
// Scan phase 3: replay chunk with carry-in, highway gate, write outputs
// (optionally also write int8 digit quantization for next layer's GEMM A)
// ---------------------------------------------------------------------------
__global__ void __launch_bounds__(256)
scan_p3(const float* __restrict__ z, const float* __restrict__ hin,
        const float* __restrict__ pf, float* __restrict__ hout,
        int8_t* __restrict__ oq1, int8_t* __restrict__ oq2, int wsplit)
{
    const int idx = blockIdx.x * blockDim.x + threadIdx.x;
    const int c = idx & (HDIM - 1);
    const int chunk = (idx >> 10) & (NC - 1);
    const int b = idx >> 15;
    const size_t row0 = (size_t)b * TLEN + (size_t)chunk * CL;
    const float* zb = z + row0 * N3H + c;
    const float* hb = hin + row0 * HDIM + c;
    float* ob = hout + row0 * HDIM + c;

    float s = pf[idx];
    #pragma unroll 4
    for (int t = 0; t < CL; ++t) {
        float zh = __ldcs(zb + (size_t)t * N3H);
        float zg = __ldcs(zb + (size_t)t * N3H + HDIM);
        float zp = __ldcs(zb + (size_t)t * N3H + 2 * HDIM);
        float h0 = hb[(size_t)t * HDIM];
        float e  = __expf(zg);
        float cf = __fdividef(1.0f, 1.0f + e);
        float sg = 1.0f - cf;
        float gv = (zh >= 0.0f) ? (zh + 0.5f) : fsig(zh);
        s = fmaf(cf, s, sg * gv);
        float gp = fsig(zp);
        float out = fmaf(gp, s - h0, h0);
        ob[(size_t)t * HDIM] = out;
        if (wsplit) {
            int8_t q1, q2;
            quant2(out, SA_SCALE, q1, q2);
            size_t o = (row0 + t) * KSZ + c;
            oq1[o] = q1;
            oq2[o] = q2;
        }
    }
}

// ---------------------------------------------------------------------------
extern "C" void kernel_launch(void* const* d_in, const int* in_sizes, int n_in,
                              void* d_out, int out_size)
{
    const float* h  = (const float*)d_in[0];
    const float* W0 = (const float*)d_in[1];
    const float* W1 = (const float*)d_in[2];
    float* out = (float*)d_out;

    float *zbuf, *hbuf, *cP, *cS, *pf;
    int8_t *a1, *a2, *w1, *w2;
    cudaGetSymbolAddress((void**)&zbuf, g_z);
    cudaGetSymbolAddress((void**)&hbuf, g_h);
    cudaGetSymbolAddress((void**)&a1, g_a1);
    cudaGetSymbolAddress((void**)&a2, g_a2);
    cudaGetSymbolAddress((void**)&w1, g_w1);
    cudaGetSymbolAddress((void**)&w2, g_w2);
    cudaGetSymbolAddress((void**)&cP, g_cP);
    cudaGetSymbolAddress((void**)&cS, g_cS);
    cudaGetSymbolAddress((void**)&pf, g_pf);

    cudaFuncSetAttribute(gemm_imma,
                         cudaFuncAttributeMaxDynamicSharedMemorySize, SMEM_DYN);

    const dim3 ggrid(N3H / GM_BN, MROWS / GM_BM);        // (24, 256)
    const int p1_blocks = (BSZ * NC * HDIM) / 256;       // 1024
    const int p2_blocks = (BSZ * HDIM) / 256;            // 32
    const int qa_blocks = (MROWS * HDIM / 4) / 256;      // 32768
    const dim3 wt_grid(N3H / 32, KSZ / 32);              // (96, 32)
    const dim3 wt_blk(32, 8);

    // ---- layer 0 ----
    quant_wt_kernel<<<wt_grid, wt_blk>>>(W0, w1, w2);
    quant_a_kernel<<<qa_blocks, 256>>>(h, a1, a2);
    gemm_imma<<<ggrid, 256, SMEM_DYN>>>(a1, a2, w1, w2, zbuf);
    scan_p1<<<p1_blocks, 256>>>(zbuf, cP, cS);
    scan_p2<<<p2_blocks, 256>>>(cP, cS, pf);
    scan_p3<<<p1_blocks, 256>>>(zbuf, h, pf, hbuf, a1, a2, 1);

    // ---- layer 1 ----
    quant_wt_kernel<<<wt_grid, wt_blk>>>(W1, w1, w2);
    gemm_imma<<<ggrid, 256, SMEM_DYN>>>(a1, a2, w1, w2, zbuf);
    scan_p1<<<p1_blocks, 256>>>(zbuf, cP, cS);
    scan_p2<<<p2_blocks, 256>>>(cP, cS, pf);
    scan_p3<<<p1_blocks, 256>>>(zbuf, hbuf, pf, out, (int8_t*)0, (int8_t*)0, 0);
}

// round 6
// speedup vs baseline: 2.9284x; 2.9284x over previous
#include <cuda_runtime.h>
#include <cuda_bf16.h>
#include <cstdint>

// ---------------------------------------------------------------------------
// Problem constants
// ---------------------------------------------------------------------------
#define BSZ   8
#define TLEN  4096
#define HDIM  1024
#define N3H   3072
#define KSZ   1024
#define MROWS (BSZ * TLEN)      // 32768
#define NC    32                // scan chunks per sequence
#define CL    (TLEN / NC)       // 128 steps per chunk

// ---------------------------------------------------------------------------
// Device scratch (no allocations allowed)
// ---------------------------------------------------------------------------
__device__ float g_z [(size_t)MROWS * N3H];      // GEMM output z
__device__ float g_h [(size_t)MROWS * HDIM];     // inter-layer h
__device__ float g_af[(size_t)MROWS * KSZ];      // A, tf32-rounded fp32
__device__ float g_wt[(size_t)N3H * KSZ];        // W^T, tf32-rounded fp32 [N,K]
__device__ float g_cP[(size_t)BSZ * NC * HDIM];  // chunk coeff product
__device__ float g_cS[(size_t)BSZ * NC * HDIM];  // chunk local scan end
__device__ float g_pf[(size_t)BSZ * NC * HDIM];  // chunk carry-in

// ---------------------------------------------------------------------------
// Helpers
// ---------------------------------------------------------------------------
__device__ __forceinline__ uint32_t smem_u32(const void* p) {
    uint32_t a;
    asm("{ .reg .u64 t; cvta.to.shared.u64 t, %1; cvt.u32.u64 %0, t; }"
        : "=r"(a) : "l"(p));
    return a;
}

__device__ __forceinline__ void cp16(uint32_t dst, const void* src) {
    asm volatile("cp.async.cg.shared.global [%0], [%1], 16;" :: "r"(dst), "l"(src));
}

__device__ __forceinline__ void ldsm4(uint32_t r[4], uint32_t addr) {
    asm volatile("ldmatrix.sync.aligned.m8n8.x4.shared.b16 {%0,%1,%2,%3}, [%4];"
        : "=r"(r[0]), "=r"(r[1]), "=r"(r[2]), "=r"(r[3]) : "r"(addr));
}

// tf32 MMA: D[16x8] += A[16x8] * B[8x8]
__device__ __forceinline__ void mma_tf32(float c[4], uint32_t a0, uint32_t a1,
                                         uint32_t a2, uint32_t a3,
                                         uint32_t b0, uint32_t b1) {
    asm volatile(
        "mma.sync.aligned.m16n8k8.row.col.f32.tf32.tf32.f32 "
        "{%0,%1,%2,%3}, {%4,%5,%6,%7}, {%8,%9}, {%0,%1,%2,%3};"
        : "+f"(c[0]), "+f"(c[1]), "+f"(c[2]), "+f"(c[3])
        : "r"(a0), "r"(a1), "r"(a2), "r"(a3), "r"(b0), "r"(b1));
}

__device__ __forceinline__ float tf32_round(float x) {
    uint32_t r;
    asm("cvt.rna.tf32.f32 %0, %1;" : "=r"(r) : "f"(x));
    return __uint_as_float(r);
}

__device__ __forceinline__ float fsig(float x) {        // sigmoid(x)
    return __fdividef(1.0f, 1.0f + __expf(-x));
}

// ---------------------------------------------------------------------------
// GEMM: C[M,3H] = A[M,K] * W[K,3H], tf32 single-term.
// A fp32 (tf32-rounded) [M,K]; B = W^T fp32 (tf32-rounded) [N,K].
// Tile 128x128, BK=32 floats (128B rows), 4-stage cp.async, 8 warps x (64x32).
// ---------------------------------------------------------------------------
#define GM_BM 128
#define GM_BN 128
#define GM_BK 32
#define STAGES 4
#define KITERS (KSZ / GM_BK)            // 32
#define OPB 16384                       // operand tile: 128 rows x 128 B
#define STB (2 * OPB)                   // stage: A,B = 32 KB
#define SMEM_DYN (STAGES * STB)         // 128 KB

// SW128 swizzle on a byte offset within a 128B-row tile
__device__ __forceinline__ uint32_t swz(uint32_t off) {
    return off ^ ((off >> 3) & 0x70);
}

__device__ __forceinline__ void load_stage(
    uint32_t sbase, int stage,
    const float* __restrict__ A, const float* __restrict__ B,
    int bm, int bn, int kt, int tid)
{
    const int k0 = kt * GM_BK;
    const uint32_t st = sbase + (uint32_t)stage * STB;
    #pragma unroll
    for (int i = 0; i < 8; ++i) {
        const int idx = tid + i * 256;          // 0 .. 2047
        const int op = idx >> 10;               // 0=A 1=B
        const int j = idx & 1023;
        const int r = j >> 3, c = j & 7;        // row, 16B-chunk
        const float* base = op ? B : A;
        const int grow = (op ? bn : bm) + r;
        const void* src = base + (size_t)grow * KSZ + k0 + c * 4;
        const uint32_t dst = st + (uint32_t)op * OPB + swz((uint32_t)(r * 128 + c * 16));
        cp16(dst, src);
    }
    asm volatile("cp.async.commit_group;" ::: "memory");
}

__global__ void __launch_bounds__(256, 1)
gemm_tf32(const float* __restrict__ A, const float* __restrict__ B,
          float* __restrict__ C)
{
    extern __shared__ char dsm[];
    const uint32_t sbase = smem_u32(dsm);

    const int tid  = threadIdx.x;
    const int lane = tid & 31;
    const int wid  = tid >> 5;
    const int wm   = wid >> 2;                 // 0..1  (64-row slab)
    const int wn   = wid & 3;                  // 0..3  (32-col slab)
    const int bm   = blockIdx.y * GM_BM;
    const int bn   = blockIdx.x * GM_BN;

    // ldmatrix lane addressing: row-within-16 and 16B half selector
    const int lrow = (lane & 7) + ((lane >> 4) << 3);   // 0..15
    const int lhalf = (lane >> 3) & 1;                   // 0/1 (16B within 32B slice)

    float acc[4][4][4];
    #pragma unroll
    for (int i = 0; i < 4; ++i)
        #pragma unroll
        for (int j = 0; j < 4; ++j)
            #pragma unroll
            for (int q = 0; q < 4; ++q) acc[i][j][q] = 0.0f;

    #pragma unroll
    for (int s = 0; s < STAGES - 1; ++s)
        load_stage(sbase, s, A, B, bm, bn, s, tid);

    for (int kt = 0; kt < KITERS; ++kt) {
        asm volatile("cp.async.wait_group %0;" :: "n"(STAGES - 2) : "memory");
        __syncthreads();

        if (kt + STAGES - 1 < KITERS)
            load_stage(sbase, (kt + STAGES - 1) & (STAGES - 1),
                       A, B, bm, bn, kt + STAGES - 1, tid);

        const uint32_t st = sbase + (uint32_t)(kt & (STAGES - 1)) * STB;

        #pragma unroll
        for (int s = 0; s < 4; ++s) {          // four k8 slices in BK=32
            const uint32_t kbyte = (uint32_t)(s * 32 + lhalf * 16);
            // A fragments: 4 x m16
            uint32_t af[4][4];
            #pragma unroll
            for (int mf = 0; mf < 4; ++mf) {
                const uint32_t row = (uint32_t)(wm * 64 + mf * 16 + lrow);
                ldsm4(af[mf], st + swz(row * 128 + kbyte));
            }
            // B fragments: 2 x n16 (each ldsm gives two n8 frags)
            #pragma unroll
            for (int j = 0; j < 2; ++j) {
                uint32_t bf[4];
                const uint32_t nrow = (uint32_t)(wn * 32 + j * 16 + lrow);
                ldsm4(bf, st + OPB + swz(nrow * 128 + kbyte));
                #pragma unroll
                for (int mf = 0; mf < 4; ++mf) {
                    mma_tf32(acc[mf][2 * j],     af[mf][0], af[mf][2], af[mf][1], af[mf][3],
                             bf[0], bf[1]);
                    mma_tf32(acc[mf][2 * j + 1], af[mf][0], af[mf][2], af[mf][1], af[mf][3],
                             bf[2], bf[3]);
                }
            }
        }
    }

    // epilogue: fp32 accumulators are the answer
    #pragma unroll
    for (int mf = 0; mf < 4; ++mf) {
        const int row = bm + wm * 64 + mf * 16 + (lane >> 2);
        #pragma unroll
        for (int nf = 0; nf < 4; ++nf) {
            const float* c = acc[mf][nf];
            const int col = bn + wn * 32 + (nf >> 1) * 16 + (nf & 1) * 8 + (lane & 3) * 2;
            *(float2*)(C + (size_t)row * N3H + col)       = make_float2(c[0], c[1]);
            *(float2*)(C + (size_t)(row + 8) * N3H + col) = make_float2(c[2], c[3]);
        }
    }
}

// ---------------------------------------------------------------------------
// tf32-round dense fp32 A
// ---------------------------------------------------------------------------
__global__ void __launch_bounds__(256)
round_a_kernel(const float* __restrict__ x, float* __restrict__ o)
{
    const size_t i = (size_t)blockIdx.x * blockDim.x + threadIdx.x;
    float4 v = ((const float4*)x)[i];
    v.x = tf32_round(v.x);
    v.y = tf32_round(v.y);
    v.z = tf32_round(v.z);
    v.w = tf32_round(v.w);
    ((float4*)o)[i] = v;
}

// ---------------------------------------------------------------------------
// transpose + tf32-round W:  W[K,3H] -> W^T[3H,K]
// ---------------------------------------------------------------------------
__global__ void __launch_bounds__(256)
trans_wt_kernel(const float* __restrict__ W, float* __restrict__ o)
{
    __shared__ float tile[32][33];
    const int n0 = blockIdx.x * 32;
    const int k0 = blockIdx.y * 32;
    const int tx = threadIdx.x, ty = threadIdx.y;   // 32 x 8
    #pragma unroll
    for (int r = ty; r < 32; r += 8)
        tile[r][tx] = W[(size_t)(k0 + r) * N3H + n0 + tx];
    __syncthreads();
    #pragma unroll
    for (int r = ty; r < 32; r += 8)
        o[(size_t)(n0 + r) * KSZ + k0 + tx] = tf32_round(tile[tx][r]);
}

// ---------------------------------------------------------------------------
// Scan phase 1: per (b, chunk, c): P = prod coeff, S = chunk-local scan end
// ---------------------------------------------------------------------------
__global__ void __launch_bounds__(256)
scan_p1(const float* __restrict__ z, float* __restrict__ cP, float* __restrict__ cS)
{
    const int idx = blockIdx.x * blockDim.x + threadIdx.x;   // B*NC*H
    const int c = idx & (HDIM - 1);
    const int chunk = (idx >> 10) & (NC - 1);
    const int b = idx >> 15;
    const float* zb = z + ((size_t)b * TLEN + (size_t)chunk * CL) * N3H + c;
    float P = 1.0f, S = 0.0f;
    #pragma unroll 8
    for (int t = 0; t < CL; ++t) {
        float zh = __ldcs(zb + (size_t)t * N3H);
        float zg = __ldcs(zb + (size_t)t * N3H + HDIM);
        float e  = __expf(zg);
        float cf = __fdividef(1.0f, 1.0f + e);       // sigmoid(-zg)
        float sg = 1.0f - cf;                        // sigmoid(zg)
        float gv = (zh >= 0.0f) ? (zh + 0.5f) : fsig(zh);
        S = fmaf(cf, S, sg * gv);
        P *= cf;
    }
    cP[idx] = P;
    cS[idx] = S;
}

// ---------------------------------------------------------------------------
// Scan phase 2: sequential combine over chunks -> carry-in per chunk
// ---------------------------------------------------------------------------
__global__ void __launch_bounds__(256)
scan_p2(const float* __restrict__ cP, const float* __restrict__ cS, float* __restrict__ pf)
{
    const int idx = blockIdx.x * blockDim.x + threadIdx.x;   // B*H
    const int c = idx & (HDIM - 1);
    const int b = idx >> 10;
    float s = 0.0f;
    #pragma unroll
    for (int j = 0; j < NC; ++j) {
        size_t o = ((size_t)(b * NC + j) << 10) + c;
        pf[o] = s;
        s = fmaf(cP[o], s, cS[o]);
    }
}

// ---------------------------------------------------------------------------
// Scan phase 3: replay chunk with carry-in, highway gate, write outputs
// (optionally also write tf32-rounded copy for next layer's GEMM A)
// ---------------------------------------------------------------------------
__global__ void __launch_bounds__(256)
scan_p3(const float* __restrict__ z, const float* __restrict__ hin,
        const float* __restrict__ pf, float* __restrict__ hout,
        float* __restrict__ oa, int wsplit)
{
    const int idx = blockIdx.x * blockDim.x + threadIdx.x;
    const int c = idx & (HDIM - 1);
    const int chunk = (idx >> 10) & (NC - 1);
    const int b = idx >> 15;
    const size_t row0 = (size_t)b * TLEN + (size_t)chunk * CL;
    const float* zb = z + row0 * N3H + c;
    const float* hb = hin + row0 * HDIM + c;
    float* ob = hout + row0 * HDIM + c;

    float s = pf[idx];
    #pragma unroll 4
    for (int t = 0; t < CL; ++t) {
        float zh = __ldcs(zb + (size_t)t * N3H);
        float zg = __ldcs(zb + (size_t)t * N3H + HDIM);
        float zp = __ldcs(zb + (size_t)t * N3H + 2 * HDIM);
        float h0 = hb[(size_t)t * HDIM];
        float e  = __expf(zg);
        float cf = __fdividef(1.0f, 1.0f + e);
        float sg = 1.0f - cf;
        float gv = (zh >= 0.0f) ? (zh + 0.5f) : fsig(zh);
        s = fmaf(cf, s, sg * gv);
        float gp = fsig(zp);
        float out = fmaf(gp, s - h0, h0);
        ob[(size_t)t * HDIM] = out;
        if (wsplit)
            oa[(row0 + t) * KSZ + c] = tf32_round(out);
    }
}

// ---------------------------------------------------------------------------
extern "C" void kernel_launch(void* const* d_in, const int* in_sizes, int n_in,
                              void* d_out, int out_size)
{
    const float* h  = (const float*)d_in[0];
    const float* W0 = (const float*)d_in[1];
    const float* W1 = (const float*)d_in[2];
    float* out = (float*)d_out;

    float *zbuf, *hbuf, *af, *wt, *cP, *cS, *pf;
    cudaGetSymbolAddress((void**)&zbuf, g_z);
    cudaGetSymbolAddress((void**)&hbuf, g_h);
    cudaGetSymbolAddress((void**)&af, g_af);
    cudaGetSymbolAddress((void**)&wt, g_wt);
    cudaGetSymbolAddress((void**)&cP, g_cP);
    cudaGetSymbolAddress((void**)&cS, g_cS);
    cudaGetSymbolAddress((void**)&pf, g_pf);

    cudaFuncSetAttribute(gemm_tf32,
                         cudaFuncAttributeMaxDynamicSharedMemorySize, SMEM_DYN);

    const dim3 ggrid(N3H / GM_BN, MROWS / GM_BM);        // (24, 256)
    const int p1_blocks = (BSZ * NC * HDIM) / 256;       // 1024
    const int p2_blocks = (BSZ * HDIM) / 256;            // 32
    const int ra_blocks = (MROWS * HDIM / 4) / 256;      // 32768
    const dim3 wt_grid(N3H / 32, KSZ / 32);              // (96, 32)
    const dim3 wt_blk(32, 8);

    // ---- layer 0 ----
    trans_wt_kernel<<<wt_grid, wt_blk>>>(W0, wt);
    round_a_kernel<<<ra_blocks, 256>>>(h, af);
    gemm_tf32<<<ggrid, 256, SMEM_DYN>>>(af, wt, zbuf);
    scan_p1<<<p1_blocks, 256>>>(zbuf, cP, cS);
    scan_p2<<<p2_blocks, 256>>>(cP, cS, pf);
    scan_p3<<<p1_blocks, 256>>>(zbuf, h, pf, hbuf, af, 1);

    // ---- layer 1 ----
    trans_wt_kernel<<<wt_grid, wt_blk>>>(W1, wt);
    gemm_tf32<<<ggrid, 256, SMEM_DYN>>>(af, wt, zbuf);
    scan_p1<<<p1_blocks, 256>>>(zbuf, cP, cS);
    scan_p2<<<p2_blocks, 256>>>(cP, cS, pf);
    scan_p3<<<p1_blocks, 256>>>(zbuf, hbuf, pf, out, (float*)0, 0);
}

// round 7
// speedup vs baseline: 3.1153x; 1.0638x over previous
#include <cuda_runtime.h>
#include <cuda_bf16.h>
#include <cstdint>

// ---------------------------------------------------------------------------
// Problem constants
// ---------------------------------------------------------------------------
#define BSZ   8
#define TLEN  4096
#define HDIM  1024
#define N3H   3072
#define KSZ   1024
#define MROWS (BSZ * TLEN)      // 32768
#define NC    32                // scan chunks per sequence
#define CL    (TLEN / NC)       // 128 steps per chunk

// ---------------------------------------------------------------------------
// Device scratch (no allocations allowed)
// ---------------------------------------------------------------------------
__device__ float g_z [(size_t)MROWS * N3H];      // GEMM output z
__device__ float g_h [(size_t)MROWS * HDIM];     // inter-layer h
__device__ float g_wt[(size_t)N3H * KSZ];        // W^T, tf32-rounded fp32 [N,K]
__device__ float g_cP[(size_t)BSZ * NC * HDIM];  // chunk coeff product
__device__ float g_cS[(size_t)BSZ * NC * HDIM];  // chunk local scan end
__device__ float g_pf[(size_t)BSZ * NC * HDIM];  // chunk carry-in

// ---------------------------------------------------------------------------
// Helpers
// ---------------------------------------------------------------------------
__device__ __forceinline__ uint32_t smem_u32(const void* p) {
    uint32_t a;
    asm("{ .reg .u64 t; cvta.to.shared.u64 t, %1; cvt.u32.u64 %0, t; }"
        : "=r"(a) : "l"(p));
    return a;
}

__device__ __forceinline__ void cp16(uint32_t dst, const void* src) {
    asm volatile("cp.async.cg.shared.global [%0], [%1], 16;" :: "r"(dst), "l"(src));
}

__device__ __forceinline__ void ldsm4(uint32_t r[4], uint32_t addr) {
    asm volatile("ldmatrix.sync.aligned.m8n8.x4.shared.b16 {%0,%1,%2,%3}, [%4];"
        : "=r"(r[0]), "=r"(r[1]), "=r"(r[2]), "=r"(r[3]) : "r"(addr));
}

// tf32 MMA: D[16x8] += A[16x8] * B[8x8]
__device__ __forceinline__ void mma_tf32(float c[4], uint32_t a0, uint32_t a1,
                                         uint32_t a2, uint32_t a3,
                                         uint32_t b0, uint32_t b1) {
    asm volatile(
        "mma.sync.aligned.m16n8k8.row.col.f32.tf32.tf32.f32 "
        "{%0,%1,%2,%3}, {%4,%5,%6,%7}, {%8,%9}, {%0,%1,%2,%3};"
        : "+f"(c[0]), "+f"(c[1]), "+f"(c[2]), "+f"(c[3])
        : "r"(a0), "r"(a1), "r"(a2), "r"(a3), "r"(b0), "r"(b1));
}

__device__ __forceinline__ float tf32_round(float x) {
    uint32_t r;
    asm("cvt.rna.tf32.f32 %0, %1;" : "=r"(r) : "f"(x));
    return __uint_as_float(r);
}

__device__ __forceinline__ uint32_t tf32_round_u(uint32_t x) {
    uint32_t r;
    asm("cvt.rna.tf32.f32 %0, %1;" : "=r"(r) : "r"(x));
    return r;
}

__device__ __forceinline__ float fsig(float x) {        // sigmoid(x)
    return __fdividef(1.0f, 1.0f + __expf(-x));
}

// ---------------------------------------------------------------------------
// GEMM: C[M,3H] = A[M,K] * W[K,3H], tf32 single-term.
// A raw fp32 [M,K] (tf32-rounded in-kernel); B = W^T tf32-rounded [N,K].
// Tile 128x128, BK=32 floats (128B rows), 3-stage cp.async, 8 warps x (64x32),
// 2 CTAs/SM.
// ---------------------------------------------------------------------------
#define GM_BM 128
#define GM_BN 128
#define GM_BK 32
#define STAGES 3
#define KITERS (KSZ / GM_BK)            // 32
#define OPB 16384                       // operand tile: 128 rows x 128 B
#define STB (2 * OPB)                   // stage: A,B = 32 KB
#define SMEM_DYN (STAGES * STB)         // 96 KB

// SW128 swizzle on a byte offset within a 128B-row tile
__device__ __forceinline__ uint32_t swz(uint32_t off) {
    return off ^ ((off >> 3) & 0x70);
}

__device__ __forceinline__ void load_stage(
    uint32_t sbase, int stage,
    const float* __restrict__ A, const float* __restrict__ B,
    int bm, int bn, int kt, int tid)
{
    const int k0 = kt * GM_BK;
    const uint32_t st = sbase + (uint32_t)stage * STB;
    #pragma unroll
    for (int i = 0; i < 8; ++i) {
        const int idx = tid + i * 256;          // 0 .. 2047
        const int op = idx >> 10;               // 0=A 1=B
        const int j = idx & 1023;
        const int r = j >> 3, c = j & 7;        // row, 16B-chunk
        const float* base = op ? B : A;
        const int grow = (op ? bn : bm) + r;
        const void* src = base + (size_t)grow * KSZ + k0 + c * 4;
        const uint32_t dst = st + (uint32_t)op * OPB + swz((uint32_t)(r * 128 + c * 16));
        cp16(dst, src);
    }
    asm volatile("cp.async.commit_group;" ::: "memory");
}

__global__ void __launch_bounds__(256, 2)
gemm_tf32(const float* __restrict__ A, const float* __restrict__ B,
          float* __restrict__ C)
{
    extern __shared__ char dsm[];
    const uint32_t sbase = smem_u32(dsm);

    const int tid  = threadIdx.x;
    const int lane = tid & 31;
    const int wid  = tid >> 5;
    const int wm   = wid >> 2;                 // 0..1  (64-row slab)
    const int wn   = wid & 3;                  // 0..3  (32-col slab)
    const int bm   = blockIdx.y * GM_BM;
    const int bn   = blockIdx.x * GM_BN;

    // ldmatrix lane addressing: row-within-16 and 16B half selector
    const int lrow = (lane & 7) + ((lane >> 4) << 3);   // 0..15
    const int lhalf = (lane >> 3) & 1;                   // 0/1 (16B within 32B slice)

    float acc[4][4][4];
    #pragma unroll
    for (int i = 0; i < 4; ++i)
        #pragma unroll
        for (int j = 0; j < 4; ++j)
            #pragma unroll
            for (int q = 0; q < 4; ++q) acc[i][j][q] = 0.0f;

    #pragma unroll
    for (int s = 0; s < STAGES - 1; ++s)
        load_stage(sbase, s, A, B, bm, bn, s, tid);

    for (int kt = 0; kt < KITERS; ++kt) {
        asm volatile("cp.async.wait_group %0;" :: "n"(STAGES - 2) : "memory");
        __syncthreads();

        if (kt + STAGES - 1 < KITERS)
            load_stage(sbase, (kt + STAGES - 1) % STAGES,
                       A, B, bm, bn, kt + STAGES - 1, tid);

        const uint32_t st = sbase + (uint32_t)(kt % STAGES) * STB;

        #pragma unroll
        for (int s = 0; s < 4; ++s) {          // four k8 slices in BK=32
            const uint32_t kbyte = (uint32_t)(s * 32 + lhalf * 16);
            // A fragments: 4 x m16, tf32-rounded in registers
            uint32_t af[4][4];
            #pragma unroll
            for (int mf = 0; mf < 4; ++mf) {
                const uint32_t row = (uint32_t)(wm * 64 + mf * 16 + lrow);
                ldsm4(af[mf], st + swz(row * 128 + kbyte));
                #pragma unroll
                for (int q = 0; q < 4; ++q) af[mf][q] = tf32_round_u(af[mf][q]);
            }
            // B fragments: 2 x n16 (each ldsm gives two n8 frags)
            #pragma unroll
            for (int j = 0; j < 2; ++j) {
                uint32_t bf[4];
                const uint32_t nrow = (uint32_t)(wn * 32 + j * 16 + lrow);
                ldsm4(bf, st + OPB + swz(nrow * 128 + kbyte));
                #pragma unroll
                for (int mf = 0; mf < 4; ++mf) {
                    mma_tf32(acc[mf][2 * j],     af[mf][0], af[mf][2], af[mf][1], af[mf][3],
                             bf[0], bf[1]);
                    mma_tf32(acc[mf][2 * j + 1], af[mf][0], af[mf][2], af[mf][1], af[mf][3],
                             bf[2], bf[3]);
                }
            }
        }
    }

    // epilogue: fp32 accumulators are the answer
    #pragma unroll
    for (int mf = 0; mf < 4; ++mf) {
        const int row = bm + wm * 64 + mf * 16 + (lane >> 2);
        #pragma unroll
        for (int nf = 0; nf < 4; ++nf) {
            const float* c = acc[mf][nf];
            const int col = bn + wn * 32 + (nf >> 1) * 16 + (nf & 1) * 8 + (lane & 3) * 2;
            *(float2*)(C + (size_t)row * N3H + col)       = make_float2(c[0], c[1]);
            *(float2*)(C + (size_t)(row + 8) * N3H + col) = make_float2(c[2], c[3]);
        }
    }
}

// ---------------------------------------------------------------------------
// transpose + tf32-round W:  W[K,3H] -> W^T[3H,K]
// ---------------------------------------------------------------------------
__global__ void __launch_bounds__(256)
trans_wt_kernel(const float* __restrict__ W, float* __restrict__ o)
{
    __shared__ float tile[32][33];
    const int n0 = blockIdx.x * 32;
    const int k0 = blockIdx.y * 32;
    const int tx = threadIdx.x, ty = threadIdx.y;   // 32 x 8
    #pragma unroll
    for (int r = ty; r < 32; r += 8)
        tile[r][tx] = W[(size_t)(k0 + r) * N3H + n0 + tx];
    __syncthreads();
    #pragma unroll
    for (int r = ty; r < 32; r += 8)
        o[(size_t)(n0 + r) * KSZ + k0 + tx] = tf32_round(tile[tx][r]);
}

// ---------------------------------------------------------------------------
// Scan phase 1: per (b, chunk, c): P = prod coeff, S = chunk-local scan end
// ---------------------------------------------------------------------------
__global__ void __launch_bounds__(256)
scan_p1(const float* __restrict__ z, float* __restrict__ cP, float* __restrict__ cS)
{
    const int idx = blockIdx.x * blockDim.x + threadIdx.x;   // B*NC*H
    const int c = idx & (HDIM - 1);
    const int chunk = (idx >> 10) & (NC - 1);
    const int b = idx >> 15;
    const float* zb = z + ((size_t)b * TLEN + (size_t)chunk * CL) * N3H + c;
    float P = 1.0f, S = 0.0f;
    #pragma unroll 8
    for (int t = 0; t < CL; ++t) {
        float zh = __ldcs(zb + (size_t)t * N3H);
        float zg = __ldcs(zb + (size_t)t * N3H + HDIM);
        float e  = __expf(zg);
        float cf = __fdividef(1.0f, 1.0f + e);       // sigmoid(-zg)
        float sg = 1.0f - cf;                        // sigmoid(zg)
        float gv = (zh >= 0.0f) ? (zh + 0.5f) : fsig(zh);
        S = fmaf(cf, S, sg * gv);
        P *= cf;
    }
    cP[idx] = P;
    cS[idx] = S;
}

// ---------------------------------------------------------------------------
// Scan phase 2: sequential combine over chunks -> carry-in per chunk
// ---------------------------------------------------------------------------
__global__ void __launch_bounds__(256)
scan_p2(const float* __restrict__ cP, const float* __restrict__ cS, float* __restrict__ pf)
{
    const int idx = blockIdx.x * blockDim.x + threadIdx.x;   // B*H
    const int c = idx & (HDIM - 1);
    const int b = idx >> 10;
    float s = 0.0f;
    #pragma unroll
    for (int j = 0; j < NC; ++j) {
        size_t o = ((size_t)(b * NC + j) << 10) + c;
        pf[o] = s;
        s = fmaf(cP[o], s, cS[o]);
    }
}

// ---------------------------------------------------------------------------
// Scan phase 3: replay chunk with carry-in, highway gate, write outputs
// ---------------------------------------------------------------------------
__global__ void __launch_bounds__(256)
scan_p3(const float* __restrict__ z, const float* __restrict__ hin,
        const float* __restrict__ pf, float* __restrict__ hout)
{
    const int idx = blockIdx.x * blockDim.x + threadIdx.x;
    const int c = idx & (HDIM - 1);
    const int chunk = (idx >> 10) & (NC - 1);
    const int b = idx >> 15;
    const size_t row0 = (size_t)b * TLEN + (size_t)chunk * CL;
    const float* zb = z + row0 * N3H + c;
    const float* hb = hin + row0 * HDIM + c;
    float* ob = hout + row0 * HDIM + c;

    float s = pf[idx];
    #pragma unroll 4
    for (int t = 0; t < CL; ++t) {
        float zh = __ldcs(zb + (size_t)t * N3H);
        float zg = __ldcs(zb + (size_t)t * N3H + HDIM);
        float zp = __ldcs(zb + (size_t)t * N3H + 2 * HDIM);
        float h0 = hb[(size_t)t * HDIM];
        float e  = __expf(zg);
        float cf = __fdividef(1.0f, 1.0f + e);
        float sg = 1.0f - cf;
        float gv = (zh >= 0.0f) ? (zh + 0.5f) : fsig(zh);
        s = fmaf(cf, s, sg * gv);
        float gp = fsig(zp);
        float out = fmaf(gp, s - h0, h0);
        ob[(size_t)t * HDIM] = out;
    }
}

// ---------------------------------------------------------------------------
extern "C" void kernel_launch(void* const* d_in, const int* in_sizes, int n_in,
                              void* d_out, int out_size)
{
    const float* h  = (const float*)d_in[0];
    const float* W0 = (const float*)d_in[1];
    const float* W1 = (const float*)d_in[2];
    float* out = (float*)d_out;

    float *zbuf, *hbuf, *wt, *cP, *cS, *pf;
    cudaGetSymbolAddress((void**)&zbuf, g_z);
    cudaGetSymbolAddress((void**)&hbuf, g_h);
    cudaGetSymbolAddress((void**)&wt, g_wt);
    cudaGetSymbolAddress((void**)&cP, g_cP);
    cudaGetSymbolAddress((void**)&cS, g_cS);
    cudaGetSymbolAddress((void**)&pf, g_pf);

    cudaFuncSetAttribute(gemm_tf32,
                         cudaFuncAttributeMaxDynamicSharedMemorySize, SMEM_DYN);

    const dim3 ggrid(N3H / GM_BN, MROWS / GM_BM);        // (24, 256)
    const int p1_blocks = (BSZ * NC * HDIM) / 256;       // 1024
    const int p2_blocks = (BSZ * HDIM) / 256;            // 32
    const dim3 wt_grid(N3H / 32, KSZ / 32);              // (96, 32)
    const dim3 wt_blk(32, 8);

    // ---- layer 0 ----
    trans_wt_kernel<<<wt_grid, wt_blk>>>(W0, wt);
    gemm_tf32<<<ggrid, 256, SMEM_DYN>>>(h, wt, zbuf);
    scan_p1<<<p1_blocks, 256>>>(zbuf, cP, cS);
    scan_p2<<<p2_blocks, 256>>>(cP, cS, pf);
    scan_p3<<<p1_blocks, 256>>>(zbuf, h, pf, hbuf);

    // ---- layer 1 ----
    trans_wt_kernel<<<wt_grid, wt_blk>>>(W1, wt);
    gemm_tf32<<<ggrid, 256, SMEM_DYN>>>(hbuf, wt, zbuf);
    scan_p1<<<p1_blocks, 256>>>(zbuf, cP, cS);
    scan_p2<<<p2_blocks, 256>>>(cP, cS, pf);
    scan_p3<<<p1_blocks, 256>>>(zbuf, hbuf, pf, out);
}

// round 8
// speedup vs baseline: 5.0886x; 1.6334x over previous
#include <cuda_runtime.h>
#include <cuda_fp16.h>
#include <cstdint>

// ---------------------------------------------------------------------------
// Problem constants
// ---------------------------------------------------------------------------
#define BSZ   8
#define TLEN  4096
#define HDIM  1024
#define N3H   3072
#define KSZ   1024
#define MROWS (BSZ * TLEN)      // 32768
#define NC    32                // scan chunks per sequence
#define CL    (TLEN / NC)       // 128 steps per chunk

// ---------------------------------------------------------------------------
// Device scratch (no allocations allowed)
// ---------------------------------------------------------------------------
__device__ float  g_z [(size_t)MROWS * N3H];      // GEMM output z
__device__ float  g_h [(size_t)MROWS * HDIM];     // inter-layer h
__device__ __half g_af[(size_t)MROWS * KSZ];      // A in fp16 [M,K]
__device__ __half g_wt[(size_t)N3H * KSZ];        // W^T in fp16 [N,K]
__device__ float  g_cP[(size_t)BSZ * NC * HDIM];  // chunk coeff product
__device__ float  g_cS[(size_t)BSZ * NC * HDIM];  // chunk local scan end
__device__ float  g_pf[(size_t)BSZ * NC * HDIM];  // chunk carry-in

// ---------------------------------------------------------------------------
// Helpers
// ---------------------------------------------------------------------------
__device__ __forceinline__ uint32_t smem_u32(const void* p) {
    uint32_t a;
    asm("{ .reg .u64 t; cvta.to.shared.u64 t, %1; cvt.u32.u64 %0, t; }"
        : "=r"(a) : "l"(p));
    return a;
}

__device__ __forceinline__ void cp16(uint32_t dst, const void* src) {
    asm volatile("cp.async.cg.shared.global [%0], [%1], 16;" :: "r"(dst), "l"(src));
}

__device__ __forceinline__ void ldsm4(uint32_t r[4], uint32_t addr) {
    asm volatile("ldmatrix.sync.aligned.m8n8.x4.shared.b16 {%0,%1,%2,%3}, [%4];"
        : "=r"(r[0]), "=r"(r[1]), "=r"(r[2]), "=r"(r[3]) : "r"(addr));
}

// fp16 MMA, fp32 accumulate: D[16x8] += A[16x16] * B[16x8]
__device__ __forceinline__ void mma_f16(float c[4], const uint32_t a[4],
                                        uint32_t b0, uint32_t b1) {
    asm volatile(
        "mma.sync.aligned.m16n8k16.row.col.f32.f16.f16.f32 "
        "{%0,%1,%2,%3}, {%4,%5,%6,%7}, {%8,%9}, {%0,%1,%2,%3};"
        : "+f"(c[0]), "+f"(c[1]), "+f"(c[2]), "+f"(c[3])
        : "r"(a[0]), "r"(a[1]), "r"(a[2]), "r"(a[3]), "r"(b0), "r"(b1));
}

__device__ __forceinline__ float fsig(float x) {        // sigmoid(x)
    return __fdividef(1.0f, 1.0f + __expf(-x));
}

// ---------------------------------------------------------------------------
// GEMM: C[M,3H] = A[M,K] * W[K,3H], fp16 operands, fp32 accumulate.
// A fp16 [M,K]; B = W^T fp16 [N,K].
// Tile 128x128, BK=32 (64B rows), 4-stage cp.async, 8 warps x (64x32),
// 2 CTAs/SM.
// ---------------------------------------------------------------------------
#define GM_BM 128
#define GM_BN 128
#define GM_BK 32
#define STAGES 4
#define KITERS (KSZ / GM_BK)            // 32
#define OPB 8192                        // operand tile: 128 rows x 64 B
#define STB (2 * OPB)                   // stage: A,B = 16 KB
#define SMEM_DYN (STAGES * STB)         // 64 KB

// smem offset within an operand tile for (k16-slice, row, 16B-group)
__device__ __forceinline__ uint32_t sw_off(int slice, int r, int g) {
    return (uint32_t)(((slice * 128 + r) * 2 + (g ^ ((r >> 2) & 1))) * 16);
}

__device__ __forceinline__ void load_stage(
    uint32_t sbase, int stage,
    const __half* __restrict__ A, const __half* __restrict__ B,
    int bm, int bn, int kt, int tid)
{
    const int k0 = kt * GM_BK;
    const uint32_t st = sbase + (uint32_t)stage * STB;
    #pragma unroll
    for (int i = 0; i < 4; ++i) {
        const int idx = tid + i * 256;          // 0 .. 1023
        const int op = idx >> 9;                // 0=A 1=B
        const int j = idx & 511;
        const int r = j >> 2, slice = (j >> 1) & 1, g = j & 1;
        const __half* base = op ? B : A;
        const int grow = (op ? bn : bm) + r;
        const void* src = base + (size_t)grow * KSZ + k0 + slice * 16 + g * 8;
        cp16(st + (uint32_t)op * OPB + sw_off(slice, r, g), src);
    }
    asm volatile("cp.async.commit_group;" ::: "memory");
}

__global__ void __launch_bounds__(256, 2)
gemm_f16(const __half* __restrict__ A, const __half* __restrict__ B,
         float* __restrict__ C)
{
    extern __shared__ char dsm[];
    const uint32_t sbase = smem_u32(dsm);

    const int tid  = threadIdx.x;
    const int lane = tid & 31;
    const int wid  = tid >> 5;
    const int wm   = wid >> 2;                 // 0..1  (64-row slab)
    const int wn   = wid & 3;                  // 0..3  (32-col slab)
    const int bm   = blockIdx.y * GM_BM;
    const int bn   = blockIdx.x * GM_BN;

    // ldmatrix lane-address components (validated layout)
    const int rowA = (lane & 7) + ((lane >> 3) & 1) * 8;
    const int gA   = lane >> 4;
    const int rowB = (lane & 7) + (lane >> 4) * 8;
    const int gB   = (lane >> 3) & 1;

    float acc[4][4][4];
    #pragma unroll
    for (int i = 0; i < 4; ++i)
        #pragma unroll
        for (int j = 0; j < 4; ++j)
            #pragma unroll
            for (int q = 0; q < 4; ++q) acc[i][j][q] = 0.0f;

    #pragma unroll
    for (int s = 0; s < STAGES - 1; ++s)
        load_stage(sbase, s, A, B, bm, bn, s, tid);

    for (int kt = 0; kt < KITERS; ++kt) {
        asm volatile("cp.async.wait_group %0;" :: "n"(STAGES - 2) : "memory");
        __syncthreads();

        if (kt + STAGES - 1 < KITERS)
            load_stage(sbase, (kt + STAGES - 1) & (STAGES - 1),
                       A, B, bm, bn, kt + STAGES - 1, tid);

        const uint32_t st = sbase + (uint32_t)(kt & (STAGES - 1)) * STB;

        #pragma unroll
        for (int slice = 0; slice < 2; ++slice) {
            uint32_t af[4][4];
            #pragma unroll
            for (int mf = 0; mf < 4; ++mf) {
                const uint32_t off = sw_off(slice, wm * 64 + mf * 16 + rowA, gA);
                ldsm4(af[mf], st + off);
            }
            #pragma unroll
            for (int n16 = 0; n16 < 2; ++n16) {
                uint32_t bf[4];
                const uint32_t offB = sw_off(slice, wn * 32 + n16 * 16 + rowB, gB);
                ldsm4(bf, st + OPB + offB);
                #pragma unroll
                for (int mf = 0; mf < 4; ++mf)
                    #pragma unroll
                    for (int h = 0; h < 2; ++h)
                        mma_f16(acc[mf][n16 * 2 + h], af[mf],
                                bf[2 * h], bf[2 * h + 1]);
            }
        }
    }

    // epilogue
    #pragma unroll
    for (int mf = 0; mf < 4; ++mf) {
        const int row = bm + wm * 64 + mf * 16 + (lane >> 2);
        #pragma unroll
        for (int nf = 0; nf < 4; ++nf) {
            const float* c = acc[mf][nf];
            const int col = bn + wn * 32 + (nf >> 1) * 16 + (nf & 1) * 8 + (lane & 3) * 2;
            *(float2*)(C + (size_t)row * N3H + col)       = make_float2(c[0], c[1]);
            *(float2*)(C + (size_t)(row + 8) * N3H + col) = make_float2(c[2], c[3]);
        }
    }
}

// ---------------------------------------------------------------------------
// fp32 -> fp16 conversion of dense A
// ---------------------------------------------------------------------------
__global__ void __launch_bounds__(256)
conv_a_kernel(const float* __restrict__ x, __half* __restrict__ o)
{
    const size_t i = (size_t)blockIdx.x * blockDim.x + threadIdx.x;
    float4 v = ((const float4*)x)[i];
    __half2 h0 = __floats2half2_rn(v.x, v.y);
    __half2 h1 = __floats2half2_rn(v.z, v.w);
    ((__half2*)o)[2 * i]     = h0;
    ((__half2*)o)[2 * i + 1] = h1;
}

// ---------------------------------------------------------------------------
// transpose + fp16-convert W:  W[K,3H] -> W^T[3H,K]
// ---------------------------------------------------------------------------
__global__ void __launch_bounds__(256)
trans_wt_kernel(const float* __restrict__ W, __half* __restrict__ o)
{
    __shared__ float tile[32][33];
    const int n0 = blockIdx.x * 32;
    const int k0 = blockIdx.y * 32;
    const int tx = threadIdx.x, ty = threadIdx.y;   // 32 x 8
    #pragma unroll
    for (int r = ty; r < 32; r += 8)
        tile[r][tx] = W[(size_t)(k0 + r) * N3H + n0 + tx];
    __syncthreads();
    #pragma unroll
    for (int r = ty; r < 32; r += 8)
        o[(size_t)(n0 + r) * KSZ + k0 + tx] = __float2half_rn(tile[tx][r]);
}

// ---------------------------------------------------------------------------
// Scan phase 1: per (b, chunk, c): P = prod coeff, S = chunk-local scan end
// ---------------------------------------------------------------------------
__global__ void __launch_bounds__(256)
scan_p1(const float* __restrict__ z, float* __restrict__ cP, float* __restrict__ cS)
{
    const int idx = blockIdx.x * blockDim.x + threadIdx.x;   // B*NC*H
    const int c = idx & (HDIM - 1);
    const int chunk = (idx >> 10) & (NC - 1);
    const int b = idx >> 15;
    const float* zb = z + ((size_t)b * TLEN + (size_t)chunk * CL) * N3H + c;
    float P = 1.0f, S = 0.0f;
    #pragma unroll 8
    for (int t = 0; t < CL; ++t) {
        float zh = __ldcs(zb + (size_t)t * N3H);
        float zg = __ldcs(zb + (size_t)t * N3H + HDIM);
        float e  = __expf(zg);
        float cf = __fdividef(1.0f, 1.0f + e);       // sigmoid(-zg)
        float sg = 1.0f - cf;                        // sigmoid(zg)
        float gv = (zh >= 0.0f) ? (zh + 0.5f) : fsig(zh);
        S = fmaf(cf, S, sg * gv);
        P *= cf;
    }
    cP[idx] = P;
    cS[idx] = S;
}

// ---------------------------------------------------------------------------
// Scan phase 2: sequential combine over chunks -> carry-in per chunk
// ---------------------------------------------------------------------------
__global__ void __launch_bounds__(256)
scan_p2(const float* __restrict__ cP, const float* __restrict__ cS, float* __restrict__ pf)
{
    const int idx = blockIdx.x * blockDim.x + threadIdx.x;   // B*H
    const int c = idx & (HDIM - 1);
    const int b = idx >> 10;
    float s = 0.0f;
    #pragma unroll
    for (int j = 0; j < NC; ++j) {
        size_t o = ((size_t)(b * NC + j) << 10) + c;
        pf[o] = s;
        s = fmaf(cP[o], s, cS[o]);
    }
}

// ---------------------------------------------------------------------------
// Scan phase 3: replay chunk with carry-in, highway gate, write outputs
// (optionally also write fp16 copy for next layer's GEMM A)
// ---------------------------------------------------------------------------
__global__ void __launch_bounds__(256)
scan_p3(const float* __restrict__ z, const float* __restrict__ hin,
        const float* __restrict__ pf, float* __restrict__ hout,
        __half* __restrict__ oa, int wsplit)
{
    const int idx = blockIdx.x * blockDim.x + threadIdx.x;
    const int c = idx & (HDIM - 1);
    const int chunk = (idx >> 10) & (NC - 1);
    const int b = idx >> 15;
    const size_t row0 = (size_t)b * TLEN + (size_t)chunk * CL;
    const float* zb = z + row0 * N3H + c;
    const float* hb = hin + row0 * HDIM + c;
    float* ob = hout + row0 * HDIM + c;

    float s = pf[idx];
    #pragma unroll 4
    for (int t = 0; t < CL; ++t) {
        float zh = __ldcs(zb + (size_t)t * N3H);
        float zg = __ldcs(zb + (size_t)t * N3H + HDIM);
        float zp = __ldcs(zb + (size_t)t * N3H + 2 * HDIM);
        float h0 = hb[(size_t)t * HDIM];
        float e  = __expf(zg);
        float cf = __fdividef(1.0f, 1.0f + e);
        float sg = 1.0f - cf;
        float gv = (zh >= 0.0f) ? (zh + 0.5f) : fsig(zh);
        s = fmaf(cf, s, sg * gv);
        float gp = fsig(zp);
        float out = fmaf(gp, s - h0, h0);
        ob[(size_t)t * HDIM] = out;
        if (wsplit)
            oa[(row0 + t) * KSZ + c] = __float2half_rn(out);
    }
}

// ---------------------------------------------------------------------------
extern "C" void kernel_launch(void* const* d_in, const int* in_sizes, int n_in,
                              void* d_out, int out_size)
{
    const float* h  = (const float*)d_in[0];
    const float* W0 = (const float*)d_in[1];
    const float* W1 = (const float*)d_in[2];
    float* out = (float*)d_out;

    float *zbuf, *hbuf, *cP, *cS, *pf;
    __half *af, *wt;
    cudaGetSymbolAddress((void**)&zbuf, g_z);
    cudaGetSymbolAddress((void**)&hbuf, g_h);
    cudaGetSymbolAddress((void**)&af, g_af);
    cudaGetSymbolAddress((void**)&wt, g_wt);
    cudaGetSymbolAddress((void**)&cP, g_cP);
    cudaGetSymbolAddress((void**)&cS, g_cS);
    cudaGetSymbolAddress((void**)&pf, g_pf);

    cudaFuncSetAttribute(gemm_f16,
                         cudaFuncAttributeMaxDynamicSharedMemorySize, SMEM_DYN);

    const dim3 ggrid(N3H / GM_BN, MROWS / GM_BM);        // (24, 256)
    const int p1_blocks = (BSZ * NC * HDIM) / 256;       // 1024
    const int p2_blocks = (BSZ * HDIM) / 256;            // 32
    const int ca_blocks = (MROWS * HDIM / 4) / 256;      // 32768
    const dim3 wt_grid(N3H / 32, KSZ / 32);              // (96, 32)
    const dim3 wt_blk(32, 8);

    // ---- layer 0 ----
    trans_wt_kernel<<<wt_grid, wt_blk>>>(W0, wt);
    conv_a_kernel<<<ca_blocks, 256>>>(h, af);
    gemm_f16<<<ggrid, 256, SMEM_DYN>>>(af, wt, zbuf);
    scan_p1<<<p1_blocks, 256>>>(zbuf, cP, cS);
    scan_p2<<<p2_blocks, 256>>>(cP, cS, pf);
    scan_p3<<<p1_blocks, 256>>>(zbuf, h, pf, hbuf, af, 1);

    // ---- layer 1 ----
    trans_wt_kernel<<<wt_grid, wt_blk>>>(W1, wt);
    gemm_f16<<<ggrid, 256, SMEM_DYN>>>(af, wt, zbuf);
    scan_p1<<<p1_blocks, 256>>>(zbuf, cP, cS);
    scan_p2<<<p2_blocks, 256>>>(cP, cS, pf);
    scan_p3<<<p1_blocks, 256>>>(zbuf, hbuf, pf, out, (__half*)0, 0);
}

// round 9
// speedup vs baseline: 5.3048x; 1.0425x over previous
#include <cuda_runtime.h>
#include <cuda_fp16.h>
#include <cstdint>

// ---------------------------------------------------------------------------
// Problem constants
// ---------------------------------------------------------------------------
#define BSZ   8
#define TLEN  4096
#define HDIM  1024
#define N3H   3072
#define KSZ   1024
#define MROWS (BSZ * TLEN)      // 32768
#define NC    32                // scan chunks per sequence
#define CL    (TLEN / NC)       // 128 steps per chunk

// ---------------------------------------------------------------------------
// Device scratch (no allocations allowed)
// ---------------------------------------------------------------------------
__device__ __half g_z [(size_t)MROWS * N3H];      // GEMM output z (fp16)
__device__ float  g_h [(size_t)MROWS * HDIM];     // inter-layer h
__device__ __half g_af[(size_t)MROWS * KSZ];      // A in fp16 [M,K]
__device__ __half g_w0[(size_t)N3H * KSZ];        // W0^T fp16 [N,K]
__device__ __half g_w1[(size_t)N3H * KSZ];        // W1^T fp16 [N,K]
__device__ float  g_cP[(size_t)BSZ * NC * HDIM];  // chunk coeff product
__device__ float  g_cS[(size_t)BSZ * NC * HDIM];  // chunk local scan end
__device__ float  g_pf[(size_t)BSZ * NC * HDIM];  // chunk carry-in

// ---------------------------------------------------------------------------
// Helpers
// ---------------------------------------------------------------------------
__device__ __forceinline__ uint32_t smem_u32(const void* p) {
    uint32_t a;
    asm("{ .reg .u64 t; cvta.to.shared.u64 t, %1; cvt.u32.u64 %0, t; }"
        : "=r"(a) : "l"(p));
    return a;
}

__device__ __forceinline__ void cp16(uint32_t dst, const void* src) {
    asm volatile("cp.async.cg.shared.global [%0], [%1], 16;" :: "r"(dst), "l"(src));
}

__device__ __forceinline__ void ldsm4(uint32_t r[4], uint32_t addr) {
    asm volatile("ldmatrix.sync.aligned.m8n8.x4.shared.b16 {%0,%1,%2,%3}, [%4];"
        : "=r"(r[0]), "=r"(r[1]), "=r"(r[2]), "=r"(r[3]) : "r"(addr));
}

// fp16 MMA, fp32 accumulate: D[16x8] += A[16x16] * B[16x8]
__device__ __forceinline__ void mma_f16(float c[4], const uint32_t a[4],
                                        uint32_t b0, uint32_t b1) {
    asm volatile(
        "mma.sync.aligned.m16n8k16.row.col.f32.f16.f16.f32 "
        "{%0,%1,%2,%3}, {%4,%5,%6,%7}, {%8,%9}, {%0,%1,%2,%3};"
        : "+f"(c[0]), "+f"(c[1]), "+f"(c[2]), "+f"(c[3])
        : "r"(a[0]), "r"(a[1]), "r"(a[2]), "r"(a[3]), "r"(b0), "r"(b1));
}

__device__ __forceinline__ float fsig(float x) {        // sigmoid(x)
    return __fdividef(1.0f, 1.0f + __expf(-x));
}

// ---------------------------------------------------------------------------
// GEMM: C[M,3H] = A[M,K] * W[K,3H], fp16 in, fp32 acc, fp16 out.
// Tile 128x128, BK=32, 4-stage cp.async, 8 warps x (64x32), 2 CTAs/SM.
// ---------------------------------------------------------------------------
#define GM_BM 128
#define GM_BN 128
#define GM_BK 32
#define STAGES 4
#define KITERS (KSZ / GM_BK)            // 32
#define OPB 8192                        // operand tile: 128 rows x 64 B
#define STB (2 * OPB)                   // stage: A,B = 16 KB
#define SMEM_DYN (STAGES * STB)         // 64 KB

// smem offset within an operand tile for (k16-slice, row, 16B-group)
__device__ __forceinline__ uint32_t sw_off(int slice, int r, int g) {
    return (uint32_t)(((slice * 128 + r) * 2 + (g ^ ((r >> 2) & 1))) * 16);
}

__device__ __forceinline__ void load_stage(
    uint32_t sbase, int stage,
    const __half* __restrict__ A, const __half* __restrict__ B,
    int bm, int bn, int kt, int tid)
{
    const int k0 = kt * GM_BK;
    const uint32_t st = sbase + (uint32_t)stage * STB;
    #pragma unroll
    for (int i = 0; i < 4; ++i) {
        const int idx = tid + i * 256;          // 0 .. 1023
        const int op = idx >> 9;                // 0=A 1=B
        const int j = idx & 511;
        const int r = j >> 2, slice = (j >> 1) & 1, g = j & 1;
        const __half* base = op ? B : A;
        const int grow = (op ? bn : bm) + r;
        const void* src = base + (size_t)grow * KSZ + k0 + slice * 16 + g * 8;
        cp16(st + (uint32_t)op * OPB + sw_off(slice, r, g), src);
    }
    asm volatile("cp.async.commit_group;" ::: "memory");
}

__global__ void __launch_bounds__(256, 2)
gemm_f16(const __half* __restrict__ A, const __half* __restrict__ B,
         __half* __restrict__ C)
{
    extern __shared__ char dsm[];
    const uint32_t sbase = smem_u32(dsm);

    const int tid  = threadIdx.x;
    const int lane = tid & 31;
    const int wid  = tid >> 5;
    const int wm   = wid >> 2;                 // 0..1  (64-row slab)
    const int wn   = wid & 3;                  // 0..3  (32-col slab)
    const int bm   = blockIdx.y * GM_BM;
    const int bn   = blockIdx.x * GM_BN;

    const int rowA = (lane & 7) + ((lane >> 3) & 1) * 8;
    const int gA   = lane >> 4;
    const int rowB = (lane & 7) + (lane >> 4) * 8;
    const int gB   = (lane >> 3) & 1;

    float acc[4][4][4];
    #pragma unroll
    for (int i = 0; i < 4; ++i)
        #pragma unroll
        for (int j = 0; j < 4; ++j)
            #pragma unroll
            for (int q = 0; q < 4; ++q) acc[i][j][q] = 0.0f;

    #pragma unroll
    for (int s = 0; s < STAGES - 1; ++s)
        load_stage(sbase, s, A, B, bm, bn, s, tid);

    for (int kt = 0; kt < KITERS; ++kt) {
        asm volatile("cp.async.wait_group %0;" :: "n"(STAGES - 2) : "memory");
        __syncthreads();

        if (kt + STAGES - 1 < KITERS)
            load_stage(sbase, (kt + STAGES - 1) & (STAGES - 1),
                       A, B, bm, bn, kt + STAGES - 1, tid);

        const uint32_t st = sbase + (uint32_t)(kt & (STAGES - 1)) * STB;

        #pragma unroll
        for (int slice = 0; slice < 2; ++slice) {
            uint32_t af[4][4];
            #pragma unroll
            for (int mf = 0; mf < 4; ++mf) {
                const uint32_t off = sw_off(slice, wm * 64 + mf * 16 + rowA, gA);
                ldsm4(af[mf], st + off);
            }
            #pragma unroll
            for (int n16 = 0; n16 < 2; ++n16) {
                uint32_t bf[4];
                const uint32_t offB = sw_off(slice, wn * 32 + n16 * 16 + rowB, gB);
                ldsm4(bf, st + OPB + offB);
                #pragma unroll
                for (int mf = 0; mf < 4; ++mf)
                    #pragma unroll
                    for (int h = 0; h < 2; ++h)
                        mma_f16(acc[mf][n16 * 2 + h], af[mf],
                                bf[2 * h], bf[2 * h + 1]);
            }
        }
    }

    // epilogue: fp32 acc -> fp16 z
    #pragma unroll
    for (int mf = 0; mf < 4; ++mf) {
        const int row = bm + wm * 64 + mf * 16 + (lane >> 2);
        #pragma unroll
        for (int nf = 0; nf < 4; ++nf) {
            const float* c = acc[mf][nf];
            const int col = bn + wn * 32 + (nf >> 1) * 16 + (nf & 1) * 8 + (lane & 3) * 2;
            *(__half2*)(C + (size_t)row * N3H + col)       = __floats2half2_rn(c[0], c[1]);
            *(__half2*)(C + (size_t)(row + 8) * N3H + col) = __floats2half2_rn(c[2], c[3]);
        }
    }
}

// ---------------------------------------------------------------------------
// Fused prologue: transpose+convert W0 and W1, convert A -> fp16.
// Grid sections: [0,3072) W0, [3072,6144) W1, [6144,38912) conv A.
// ---------------------------------------------------------------------------
#define WT_BLOCKS 3072            // (3072/32) * (1024/32)
#define CA_BLOCKS 32768           // MROWS*HDIM/4/256

__global__ void __launch_bounds__(256)
prep_kernel(const float* __restrict__ W0, const float* __restrict__ W1,
            const float* __restrict__ h,
            __half* __restrict__ w0t, __half* __restrict__ w1t,
            __half* __restrict__ af)
{
    const int bi = blockIdx.x;
    if (bi < 2 * WT_BLOCKS) {
        __shared__ float tile[32][33];
        const float* W = (bi < WT_BLOCKS) ? W0 : W1;
        __half* o = (bi < WT_BLOCKS) ? w0t : w1t;
        const int lb = (bi < WT_BLOCKS) ? bi : bi - WT_BLOCKS;
        const int n0 = (lb % 96) * 32;
        const int k0 = (lb / 96) * 32;
        const int tx = threadIdx.x & 31, ty = threadIdx.x >> 5;   // 32 x 8
        #pragma unroll
        for (int r = ty; r < 32; r += 8)
            tile[r][tx] = W[(size_t)(k0 + r) * N3H + n0 + tx];
        __syncthreads();
        #pragma unroll
        for (int r = ty; r < 32; r += 8)
            o[(size_t)(n0 + r) * KSZ + k0 + tx] = __float2half_rn(tile[tx][r]);
    } else {
        const size_t i = (size_t)(bi - 2 * WT_BLOCKS) * 256 + threadIdx.x;
        float4 v = ((const float4*)h)[i];
        ((__half2*)af)[2 * i]     = __floats2half2_rn(v.x, v.y);
        ((__half2*)af)[2 * i + 1] = __floats2half2_rn(v.z, v.w);
    }
}

// ---------------------------------------------------------------------------
// Scan phase 1: per (b, chunk, c): P = prod coeff, S = chunk-local scan end
// ---------------------------------------------------------------------------
__global__ void __launch_bounds__(256)
scan_p1(const __half* __restrict__ z, float* __restrict__ cP, float* __restrict__ cS)
{
    const int idx = blockIdx.x * blockDim.x + threadIdx.x;   // B*NC*H
    const int c = idx & (HDIM - 1);
    const int chunk = (idx >> 10) & (NC - 1);
    const int b = idx >> 15;
    const __half* zb = z + ((size_t)b * TLEN + (size_t)chunk * CL) * N3H + c;
    float P = 1.0f, S = 0.0f;
    #pragma unroll 8
    for (int t = 0; t < CL; ++t) {
        float zh = __half2float(zb[(size_t)t * N3H]);
        float zg = __half2float(zb[(size_t)t * N3H + HDIM]);
        float e  = __expf(zg);
        float cf = __fdividef(1.0f, 1.0f + e);       // sigmoid(-zg)
        float sg = 1.0f - cf;                        // sigmoid(zg)
        float gv = (zh >= 0.0f) ? (zh + 0.5f) : fsig(zh);
        S = fmaf(cf, S, sg * gv);
        P *= cf;
    }
    cP[idx] = P;
    cS[idx] = S;
}

// ---------------------------------------------------------------------------
// Scan phase 2: sequential combine over chunks -> carry-in per chunk
// ---------------------------------------------------------------------------
__global__ void __launch_bounds__(256)
scan_p2(const float* __restrict__ cP, const float* __restrict__ cS, float* __restrict__ pf)
{
    const int idx = blockIdx.x * blockDim.x + threadIdx.x;   // B*H
    const int c = idx & (HDIM - 1);
    const int b = idx >> 10;
    float s = 0.0f;
    #pragma unroll
    for (int j = 0; j < NC; ++j) {
        size_t o = ((size_t)(b * NC + j) << 10) + c;
        pf[o] = s;
        s = fmaf(cP[o], s, cS[o]);
    }
}

// ---------------------------------------------------------------------------
// Scan phase 3: replay chunk with carry-in, highway gate, write outputs
// (optionally also write fp16 copy for next layer's GEMM A)
// ---------------------------------------------------------------------------
__global__ void __launch_bounds__(256)
scan_p3(const __half* __restrict__ z, const float* __restrict__ hin,
        const float* __restrict__ pf, float* __restrict__ hout,
        __half* __restrict__ oa, int wsplit)
{
    const int idx = blockIdx.x * blockDim.x + threadIdx.x;
    const int c = idx & (HDIM - 1);
    const int chunk = (idx >> 10) & (NC - 1);
    const int b = idx >> 15;
    const size_t row0 = (size_t)b * TLEN + (size_t)chunk * CL;
    const __half* zb = z + row0 * N3H + c;
    const float* hb = hin + row0 * HDIM + c;
    float* ob = hout + row0 * HDIM + c;

    float s = pf[idx];
    #pragma unroll 4
    for (int t = 0; t < CL; ++t) {
        float zh = __half2float(zb[(size_t)t * N3H]);
        float zg = __half2float(zb[(size_t)t * N3H + HDIM]);
        float zp = __half2float(zb[(size_t)t * N3H + 2 * HDIM]);
        float h0 = hb[(size_t)t * HDIM];
        float e  = __expf(zg);
        float cf = __fdividef(1.0f, 1.0f + e);
        float sg = 1.0f - cf;
        float gv = (zh >= 0.0f) ? (zh + 0.5f) : fsig(zh);
        s = fmaf(cf, s, sg * gv);
        float gp = fsig(zp);
        float out = fmaf(gp, s - h0, h0);
        ob[(size_t)t * HDIM] = out;
        if (wsplit)
            oa[(row0 + t) * KSZ + c] = __float2half_rn(out);
    }
}

// ---------------------------------------------------------------------------
extern "C" void kernel_launch(void* const* d_in, const int* in_sizes, int n_in,
                              void* d_out, int out_size)
{
    const float* h  = (const float*)d_in[0];
    const float* W0 = (const float*)d_in[1];
    const float* W1 = (const float*)d_in[2];
    float* out = (float*)d_out;

    float *hbuf, *cP, *cS, *pf;
    __half *zbuf, *af, *w0t, *w1t;
    cudaGetSymbolAddress((void**)&zbuf, g_z);
    cudaGetSymbolAddress((void**)&hbuf, g_h);
    cudaGetSymbolAddress((void**)&af, g_af);
    cudaGetSymbolAddress((void**)&w0t, g_w0);
    cudaGetSymbolAddress((void**)&w1t, g_w1);
    cudaGetSymbolAddress((void**)&cP, g_cP);
    cudaGetSymbolAddress((void**)&cS, g_cS);
    cudaGetSymbolAddress((void**)&pf, g_pf);

    cudaFuncSetAttribute(gemm_f16,
                         cudaFuncAttributeMaxDynamicSharedMemorySize, SMEM_DYN);

    const dim3 ggrid(N3H / GM_BN, MROWS / GM_BM);        // (24, 256)
    const int p1_blocks = (BSZ * NC * HDIM) / 256;       // 1024
    const int p2_blocks = (BSZ * HDIM) / 256;            // 32

    // fused prologue (both W transposes + A conversion)
    prep_kernel<<<2 * WT_BLOCKS + CA_BLOCKS, 256>>>(W0, W1, h, w0t, w1t, af);

    // ---- layer 0 ----
    gemm_f16<<<ggrid, 256, SMEM_DYN>>>(af, w0t, zbuf);
    scan_p1<<<p1_blocks, 256>>>(zbuf, cP, cS);
    scan_p2<<<p2_blocks, 256>>>(cP, cS, pf);
    scan_p3<<<p1_blocks, 256>>>(zbuf, h, pf, hbuf, af, 1);

    // ---- layer 1 ----
    gemm_f16<<<ggrid, 256, SMEM_DYN>>>(af, w1t, zbuf);
    scan_p1<<<p1_blocks, 256>>>(zbuf, cP, cS);
    scan_p2<<<p2_blocks, 256>>>(cP, cS, pf);
    scan_p3<<<p1_blocks, 256>>>(zbuf, hbuf, pf, out, (__half*)0, 0);
}

// round 10
// speedup vs baseline: 5.4938x; 1.0356x over previous
#include <cuda_runtime.h>
#include <cuda_fp16.h>
#include <cstdint>

// ---------------------------------------------------------------------------
// Problem constants
// ---------------------------------------------------------------------------
#define BSZ   8
#define TLEN  4096
#define HDIM  1024
#define N3H   3072
#define KSZ   1024
#define MROWS (BSZ * TLEN)      // 32768
#define NC    32                // scan chunks per sequence
#define CL    (TLEN / NC)       // 128 steps per chunk

// ---------------------------------------------------------------------------
// Device scratch (no allocations allowed)
// ---------------------------------------------------------------------------
__device__ __half g_z [(size_t)MROWS * N3H];      // GEMM output z (fp16)
__device__ __half g_af[(size_t)MROWS * KSZ];      // A fp16 [M,K]; also inter-layer h
__device__ __half g_w0[(size_t)N3H * KSZ];        // W0^T fp16 [N,K]
__device__ __half g_w1[(size_t)N3H * KSZ];        // W1^T fp16 [N,K]
__device__ float  g_cP[(size_t)BSZ * NC * HDIM];  // chunk coeff product
__device__ float  g_cS[(size_t)BSZ * NC * HDIM];  // chunk local scan end
__device__ float  g_pf[(size_t)BSZ * NC * HDIM];  // chunk carry-in

// ---------------------------------------------------------------------------
// Helpers
// ---------------------------------------------------------------------------
__device__ __forceinline__ uint32_t smem_u32(const void* p) {
    uint32_t a;
    asm("{ .reg .u64 t; cvta.to.shared.u64 t, %1; cvt.u32.u64 %0, t; }"
        : "=r"(a) : "l"(p));
    return a;
}

__device__ __forceinline__ void cp16(uint32_t dst, const void* src) {
    asm volatile("cp.async.cg.shared.global [%0], [%1], 16;" :: "r"(dst), "l"(src));
}

__device__ __forceinline__ void ldsm4(uint32_t r[4], uint32_t addr) {
    asm volatile("ldmatrix.sync.aligned.m8n8.x4.shared.b16 {%0,%1,%2,%3}, [%4];"
        : "=r"(r[0]), "=r"(r[1]), "=r"(r[2]), "=r"(r[3]) : "r"(addr));
}

// fp16 MMA, fp32 accumulate
__device__ __forceinline__ void mma_f16(float c[4], const uint32_t a[4],
                                        uint32_t b0, uint32_t b1) {
    asm volatile(
        "mma.sync.aligned.m16n8k16.row.col.f32.f16.f16.f32 "
        "{%0,%1,%2,%3}, {%4,%5,%6,%7}, {%8,%9}, {%0,%1,%2,%3};"
        : "+f"(c[0]), "+f"(c[1]), "+f"(c[2]), "+f"(c[3])
        : "r"(a[0]), "r"(a[1]), "r"(a[2]), "r"(a[3]), "r"(b0), "r"(b1));
}

__device__ __forceinline__ float fsig(float x) {        // sigmoid(x)
    return __fdividef(1.0f, 1.0f + __expf(-x));
}

// per-channel scan step pieces
__device__ __forceinline__ void gate_terms(float zh, float zg,
                                           float& cf, float& val) {
    float e  = __expf(zg);
    cf = __fdividef(1.0f, 1.0f + e);          // sigmoid(-zg)
    float sg = 1.0f - cf;                     // sigmoid(zg)
    float gv = (zh >= 0.0f) ? (zh + 0.5f) : fsig(zh);
    val = sg * gv;
}

// ---------------------------------------------------------------------------
// GEMM: C[M,3H] = A[M,K] * W[K,3H], fp16 in, fp32 acc, fp16 out.
// Tile 128x128, BK=32, 4-stage cp.async, 8 warps x (64x32), 2 CTAs/SM.
// ---------------------------------------------------------------------------
#define GM_BM 128
#define GM_BN 128
#define GM_BK 32
#define STAGES 4
#define KITERS (KSZ / GM_BK)            // 32
#define OPB 8192                        // operand tile: 128 rows x 64 B
#define STB (2 * OPB)                   // stage: A,B = 16 KB
#define SMEM_DYN (STAGES * STB)         // 64 KB

__device__ __forceinline__ uint32_t sw_off(int slice, int r, int g) {
    return (uint32_t)(((slice * 128 + r) * 2 + (g ^ ((r >> 2) & 1))) * 16);
}

__device__ __forceinline__ void load_stage(
    uint32_t sbase, int stage,
    const __half* __restrict__ A, const __half* __restrict__ B,
    int bm, int bn, int kt, int tid)
{
    const int k0 = kt * GM_BK;
    const uint32_t st = sbase + (uint32_t)stage * STB;
    #pragma unroll
    for (int i = 0; i < 4; ++i) {
        const int idx = tid + i * 256;          // 0 .. 1023
        const int op = idx >> 9;                // 0=A 1=B
        const int j = idx & 511;
        const int r = j >> 2, slice = (j >> 1) & 1, g = j & 1;
        const __half* base = op ? B : A;
        const int grow = (op ? bn : bm) + r;
        const void* src = base + (size_t)grow * KSZ + k0 + slice * 16 + g * 8;
        cp16(st + (uint32_t)op * OPB + sw_off(slice, r, g), src);
    }
    asm volatile("cp.async.commit_group;" ::: "memory");
}

__global__ void __launch_bounds__(256, 2)
gemm_f16(const __half* __restrict__ A, const __half* __restrict__ B,
         __half* __restrict__ C)
{
    extern __shared__ char dsm[];
    const uint32_t sbase = smem_u32(dsm);

    const int tid  = threadIdx.x;
    const int lane = tid & 31;
    const int wid  = tid >> 5;
    const int wm   = wid >> 2;
    const int wn   = wid & 3;
    const int bm   = blockIdx.y * GM_BM;
    const int bn   = blockIdx.x * GM_BN;

    const int rowA = (lane & 7) + ((lane >> 3) & 1) * 8;
    const int gA   = lane >> 4;
    const int rowB = (lane & 7) + (lane >> 4) * 8;
    const int gB   = (lane >> 3) & 1;

    float acc[4][4][4];
    #pragma unroll
    for (int i = 0; i < 4; ++i)
        #pragma unroll
        for (int j = 0; j < 4; ++j)
            #pragma unroll
            for (int q = 0; q < 4; ++q) acc[i][j][q] = 0.0f;

    #pragma unroll
    for (int s = 0; s < STAGES - 1; ++s)
        load_stage(sbase, s, A, B, bm, bn, s, tid);

    for (int kt = 0; kt < KITERS; ++kt) {
        asm volatile("cp.async.wait_group %0;" :: "n"(STAGES - 2) : "memory");
        __syncthreads();

        if (kt + STAGES - 1 < KITERS)
            load_stage(sbase, (kt + STAGES - 1) & (STAGES - 1),
                       A, B, bm, bn, kt + STAGES - 1, tid);

        const uint32_t st = sbase + (uint32_t)(kt & (STAGES - 1)) * STB;

        #pragma unroll
        for (int slice = 0; slice < 2; ++slice) {
            uint32_t af[4][4];
            #pragma unroll
            for (int mf = 0; mf < 4; ++mf) {
                const uint32_t off = sw_off(slice, wm * 64 + mf * 16 + rowA, gA);
                ldsm4(af[mf], st + off);
            }
            #pragma unroll
            for (int n16 = 0; n16 < 2; ++n16) {
                uint32_t bf[4];
                const uint32_t offB = sw_off(slice, wn * 32 + n16 * 16 + rowB, gB);
                ldsm4(bf, st + OPB + offB);
                #pragma unroll
                for (int mf = 0; mf < 4; ++mf)
                    #pragma unroll
                    for (int h = 0; h < 2; ++h)
                        mma_f16(acc[mf][n16 * 2 + h], af[mf],
                                bf[2 * h], bf[2 * h + 1]);
            }
        }
    }

    #pragma unroll
    for (int mf = 0; mf < 4; ++mf) {
        const int row = bm + wm * 64 + mf * 16 + (lane >> 2);
        #pragma unroll
        for (int nf = 0; nf < 4; ++nf) {
            const float* c = acc[mf][nf];
            const int col = bn + wn * 32 + (nf >> 1) * 16 + (nf & 1) * 8 + (lane & 3) * 2;
            *(__half2*)(C + (size_t)row * N3H + col)       = __floats2half2_rn(c[0], c[1]);
            *(__half2*)(C + (size_t)(row + 8) * N3H + col) = __floats2half2_rn(c[2], c[3]);
        }
    }
}

// ---------------------------------------------------------------------------
// Fused prologue: transpose+convert W0 and W1, convert A -> fp16.
// ---------------------------------------------------------------------------
#define WT_BLOCKS 3072            // (3072/32) * (1024/32)
#define CA_BLOCKS 32768           // MROWS*HDIM/4/256

__global__ void __launch_bounds__(256)
prep_kernel(const float* __restrict__ W0, const float* __restrict__ W1,
            const float* __restrict__ h,
            __half* __restrict__ w0t, __half* __restrict__ w1t,
            __half* __restrict__ af)
{
    const int bi = blockIdx.x;
    if (bi < 2 * WT_BLOCKS) {
        __shared__ float tile[32][33];
        const float* W = (bi < WT_BLOCKS) ? W0 : W1;
        __half* o = (bi < WT_BLOCKS) ? w0t : w1t;
        const int lb = (bi < WT_BLOCKS) ? bi : bi - WT_BLOCKS;
        const int n0 = (lb % 96) * 32;
        const int k0 = (lb / 96) * 32;
        const int tx = threadIdx.x & 31, ty = threadIdx.x >> 5;
        #pragma unroll
        for (int r = ty; r < 32; r += 8)
            tile[r][tx] = W[(size_t)(k0 + r) * N3H + n0 + tx];
        __syncthreads();
        #pragma unroll
        for (int r = ty; r < 32; r += 8)
            o[(size_t)(n0 + r) * KSZ + k0 + tx] = __float2half_rn(tile[tx][r]);
    } else {
        const size_t i = (size_t)(bi - 2 * WT_BLOCKS) * 256 + threadIdx.x;
        float4 v = ((const float4*)h)[i];
        ((__half2*)af)[2 * i]     = __floats2half2_rn(v.x, v.y);
        ((__half2*)af)[2 * i + 1] = __floats2half2_rn(v.z, v.w);
    }
}

// ---------------------------------------------------------------------------
// Scan phase 1 (2 channels/thread): P = prod coeff, S = chunk-local scan end
// ---------------------------------------------------------------------------
__global__ void __launch_bounds__(256)
scan_p1(const __half* __restrict__ z, float* __restrict__ cP, float* __restrict__ cS)
{
    const int idx = blockIdx.x * blockDim.x + threadIdx.x;   // B*NC*512
    const int cp2 = idx & 511;               // channel pair
    const int chunk = (idx >> 9) & (NC - 1);
    const int b = idx >> 14;
    const __half* zb = z + ((size_t)b * TLEN + (size_t)chunk * CL) * N3H + cp2 * 2;
    float P0 = 1.0f, S0 = 0.0f, P1 = 1.0f, S1 = 0.0f;
    #pragma unroll 4
    for (int t = 0; t < CL; ++t) {
        float2 zh = __half22float2(*(const __half2*)(zb + (size_t)t * N3H));
        float2 zg = __half22float2(*(const __half2*)(zb + (size_t)t * N3H + HDIM));
        float cf, val;
        gate_terms(zh.x, zg.x, cf, val);
        S0 = fmaf(cf, S0, val);  P0 *= cf;
        gate_terms(zh.y, zg.y, cf, val);
        S1 = fmaf(cf, S1, val);  P1 *= cf;
    }
    const size_t o = (((size_t)(b * NC + chunk)) << 10) + cp2 * 2;
    *(float2*)(cP + o) = make_float2(P0, P1);
    *(float2*)(cS + o) = make_float2(S0, S1);
}

// ---------------------------------------------------------------------------
// Scan phase 2 (2 channels/thread): combine over chunks -> carry-in per chunk
// ---------------------------------------------------------------------------
__global__ void __launch_bounds__(256)
scan_p2(const float* __restrict__ cP, const float* __restrict__ cS, float* __restrict__ pf)
{
    const int idx = blockIdx.x * blockDim.x + threadIdx.x;   // B*512
    const int cp2 = idx & 511;
    const int b = idx >> 9;
    float s0 = 0.0f, s1 = 0.0f;
    #pragma unroll
    for (int j = 0; j < NC; ++j) {
        const size_t o = (((size_t)(b * NC + j)) << 10) + cp2 * 2;
        *(float2*)(pf + o) = make_float2(s0, s1);
        float2 P = *(const float2*)(cP + o);
        float2 S = *(const float2*)(cS + o);
        s0 = fmaf(P.x, s0, S.x);
        s1 = fmaf(P.y, s1, S.y);
    }
}

// ---------------------------------------------------------------------------
// Scan phase 3 (2 channels/thread): replay with carry, highway gate.
// layer==0: h0 from fp32 hin32, write fp16 af (next layer A and h).
// layer==1: h0 from fp16 hin16 (==af), write fp32 out.
// ---------------------------------------------------------------------------
__global__ void __launch_bounds__(256)
scan_p3(const __half* __restrict__ z, const float* __restrict__ hin32,
        const __half* __restrict__ hin16, const float* __restrict__ pf,
        float* __restrict__ out32, __half* __restrict__ oa16, int layer)
{
    const int idx = blockIdx.x * blockDim.x + threadIdx.x;   // B*NC*512
    const int cp2 = idx & 511;
    const int chunk = (idx >> 9) & (NC - 1);
    const int b = idx >> 14;
    const size_t row0 = (size_t)b * TLEN + (size_t)chunk * CL;
    const __half* zb = z + row0 * N3H + cp2 * 2;

    const size_t po = (((size_t)(b * NC + chunk)) << 10) + cp2 * 2;
    float2 sv = *(const float2*)(pf + po);
    float s0 = sv.x, s1 = sv.y;

    #pragma unroll 4
    for (int t = 0; t < CL; ++t) {
        float2 zh = __half22float2(*(const __half2*)(zb + (size_t)t * N3H));
        float2 zg = __half22float2(*(const __half2*)(zb + (size_t)t * N3H + HDIM));
        float2 zp = __half22float2(*(const __half2*)(zb + (size_t)t * N3H + 2 * HDIM));
        float2 h0;
        const size_t ho = (row0 + t) * HDIM + cp2 * 2;
        if (layer == 0) h0 = *(const float2*)(hin32 + ho);
        else            h0 = __half22float2(*(const __half2*)(hin16 + ho));

        float cf, val;
        gate_terms(zh.x, zg.x, cf, val);
        s0 = fmaf(cf, s0, val);
        gate_terms(zh.y, zg.y, cf, val);
        s1 = fmaf(cf, s1, val);

        float gp0 = fsig(zp.x), gp1 = fsig(zp.y);
        float o0 = fmaf(gp0, s0 - h0.x, h0.x);
        float o1 = fmaf(gp1, s1 - h0.y, h0.y);

        if (layer == 0)
            *(__half2*)(oa16 + ho) = __floats2half2_rn(o0, o1);
        else
            *(float2*)(out32 + ho) = make_float2(o0, o1);
    }
}

// ---------------------------------------------------------------------------
extern "C" void kernel_launch(void* const* d_in, const int* in_sizes, int n_in,
                              void* d_out, int out_size)
{
    const float* h  = (const float*)d_in[0];
    const float* W0 = (const float*)d_in[1];
    const float* W1 = (const float*)d_in[2];
    float* out = (float*)d_out;

    float *cP, *cS, *pf;
    __half *zbuf, *af, *w0t, *w1t;
    cudaGetSymbolAddress((void**)&zbuf, g_z);
    cudaGetSymbolAddress((void**)&af, g_af);
    cudaGetSymbolAddress((void**)&w0t, g_w0);
    cudaGetSymbolAddress((void**)&w1t, g_w1);
    cudaGetSymbolAddress((void**)&cP, g_cP);
    cudaGetSymbolAddress((void**)&cS, g_cS);
    cudaGetSymbolAddress((void**)&pf, g_pf);

    cudaFuncSetAttribute(gemm_f16,
                         cudaFuncAttributeMaxDynamicSharedMemorySize, SMEM_DYN);

    const dim3 ggrid(N3H / GM_BN, MROWS / GM_BM);        // (24, 256)
    const int p1_blocks = (BSZ * NC * HDIM / 2) / 256;   // 512
    const int p2_blocks = (BSZ * HDIM / 2) / 256;        // 16

    prep_kernel<<<2 * WT_BLOCKS + CA_BLOCKS, 256>>>(W0, W1, h, w0t, w1t, af);

    // ---- layer 0 ----
    gemm_f16<<<ggrid, 256, SMEM_DYN>>>(af, w0t, zbuf);
    scan_p1<<<p1_blocks, 256>>>(zbuf, cP, cS);
    scan_p2<<<p2_blocks, 256>>>(cP, cS, pf);
    scan_p3<<<p1_blocks, 256>>>(zbuf, h, (const __half*)0, pf, (float*)0, af, 0);

    // ---- layer 1 ----
    gemm_f16<<<ggrid, 256, SMEM_DYN>>>(af, w1t, zbuf);
    scan_p1<<<p1_blocks, 256>>>(zbuf, cP, cS);
    scan_p2<<<p2_blocks, 256>>>(cP, cS, pf);
    scan_p3<<<p1_blocks, 256>>>(zbuf, (const float*)0, af, pf, out, (__half*)0, 1);
}

// round 11
// speedup vs baseline: 5.5334x; 1.0072x over previous
#include <cuda_runtime.h>
#include <cuda_fp16.h>
#include <cstdint>

// ---------------------------------------------------------------------------
// Problem constants
// ---------------------------------------------------------------------------
#define BSZ   8
#define TLEN  4096
#define HDIM  1024
#define N3H   3072
#define KSZ   1024
#define MROWS (BSZ * TLEN)      // 32768
#define NC    32                // scan chunks per sequence
#define CL    (TLEN / NC)       // 128 steps per chunk

// ---------------------------------------------------------------------------
// Device scratch (no allocations allowed)
// ---------------------------------------------------------------------------
__device__ __half g_z [(size_t)MROWS * N3H];      // transformed gates (fp16)
                                                  // [.|0..1023]=gv  [1024..2047]=cf  [2048..]=gp
__device__ __half g_af[(size_t)MROWS * KSZ];      // A fp16 [M,K]; also inter-layer h
__device__ __half g_w0[(size_t)N3H * KSZ];        // W0^T fp16 [N,K]
__device__ __half g_w1[(size_t)N3H * KSZ];        // W1^T fp16 [N,K]
__device__ float  g_cP[(size_t)BSZ * NC * HDIM];  // chunk coeff product
__device__ float  g_cS[(size_t)BSZ * NC * HDIM];  // chunk local scan end

// ---------------------------------------------------------------------------
// Helpers
// ---------------------------------------------------------------------------
__device__ __forceinline__ uint32_t smem_u32(const void* p) {
    uint32_t a;
    asm("{ .reg .u64 t; cvta.to.shared.u64 t, %1; cvt.u32.u64 %0, t; }"
        : "=r"(a) : "l"(p));
    return a;
}

__device__ __forceinline__ void cp16(uint32_t dst, const void* src) {
    asm volatile("cp.async.cg.shared.global [%0], [%1], 16;" :: "r"(dst), "l"(src));
}

__device__ __forceinline__ void ldsm4(uint32_t r[4], uint32_t addr) {
    asm volatile("ldmatrix.sync.aligned.m8n8.x4.shared.b16 {%0,%1,%2,%3}, [%4];"
        : "=r"(r[0]), "=r"(r[1]), "=r"(r[2]), "=r"(r[3]) : "r"(addr));
}

// fp16 MMA, fp32 accumulate
__device__ __forceinline__ void mma_f16(float c[4], const uint32_t a[4],
                                        uint32_t b0, uint32_t b1) {
    asm volatile(
        "mma.sync.aligned.m16n8k16.row.col.f32.f16.f16.f32 "
        "{%0,%1,%2,%3}, {%4,%5,%6,%7}, {%8,%9}, {%0,%1,%2,%3};"
        : "+f"(c[0]), "+f"(c[1]), "+f"(c[2]), "+f"(c[3])
        : "r"(a[0]), "r"(a[1]), "r"(a[2]), "r"(a[3]), "r"(b0), "r"(b1));
}

__device__ __forceinline__ float fsig(float x) {        // sigmoid(x)
    return __fdividef(1.0f, 1.0f + __expf(-x));
}

// per-section gate transform applied in the GEMM epilogue
// mode 0 (hidden): gv = g(x);  mode 1 (gate): cf = sigmoid(-x);  mode 2: gp = sigmoid(x)
__device__ __forceinline__ float gate_xform(float v, int mode) {
    if (mode == 0) return (v >= 0.0f) ? (v + 0.5f) : fsig(v);
    if (mode == 1) return __fdividef(1.0f, 1.0f + __expf(v));
    return fsig(v);
}

// ---------------------------------------------------------------------------
// GEMM: z'[M,3H] = xform(A[M,K] * W[K,3H]), fp16 in, fp32 acc, fp16 out.
// Tile 128x128, BK=32, 4-stage cp.async, 8 warps x (64x32), 2 CTAs/SM.
// ---------------------------------------------------------------------------
#define GM_BM 128
#define GM_BN 128
#define GM_BK 32
#define STAGES 4
#define KITERS (KSZ / GM_BK)            // 32
#define OPB 8192                        // operand tile: 128 rows x 64 B
#define STB (2 * OPB)                   // stage: A,B = 16 KB
#define SMEM_DYN (STAGES * STB)         // 64 KB

__device__ __forceinline__ uint32_t sw_off(int slice, int r, int g) {
    return (uint32_t)(((slice * 128 + r) * 2 + (g ^ ((r >> 2) & 1))) * 16);
}

__device__ __forceinline__ void load_stage(
    uint32_t sbase, int stage,
    const __half* __restrict__ A, const __half* __restrict__ B,
    int bm, int bn, int kt, int tid)
{
    const int k0 = kt * GM_BK;
    const uint32_t st = sbase + (uint32_t)stage * STB;
    #pragma unroll
    for (int i = 0; i < 4; ++i) {
        const int idx = tid + i * 256;          // 0 .. 1023
        const int op = idx >> 9;                // 0=A 1=B
        const int j = idx & 511;
        const int r = j >> 2, slice = (j >> 1) & 1, g = j & 1;
        const __half* base = op ? B : A;
        const int grow = (op ? bn : bm) + r;
        const void* src = base + (size_t)grow * KSZ + k0 + slice * 16 + g * 8;
        cp16(st + (uint32_t)op * OPB + sw_off(slice, r, g), src);
    }
    asm volatile("cp.async.commit_group;" ::: "memory");
}

__global__ void __launch_bounds__(256, 2)
gemm_f16(const __half* __restrict__ A, const __half* __restrict__ B,
         __half* __restrict__ C)
{
    extern __shared__ char dsm[];
    const uint32_t sbase = smem_u32(dsm);

    const int tid  = threadIdx.x;
    const int lane = tid & 31;
    const int wid  = tid >> 5;
    const int wm   = wid >> 2;
    const int wn   = wid & 3;
    const int bm   = blockIdx.y * GM_BM;
    const int bn   = blockIdx.x * GM_BN;

    const int rowA = (lane & 7) + ((lane >> 3) & 1) * 8;
    const int gA   = lane >> 4;
    const int rowB = (lane & 7) + (lane >> 4) * 8;
    const int gB   = (lane >> 3) & 1;

    float acc[4][4][4];
    #pragma unroll
    for (int i = 0; i < 4; ++i)
        #pragma unroll
        for (int j = 0; j < 4; ++j)
            #pragma unroll
            for (int q = 0; q < 4; ++q) acc[i][j][q] = 0.0f;

    #pragma unroll
    for (int s = 0; s < STAGES - 1; ++s)
        load_stage(sbase, s, A, B, bm, bn, s, tid);

    for (int kt = 0; kt < KITERS; ++kt) {
        asm volatile("cp.async.wait_group %0;" :: "n"(STAGES - 2) : "memory");
        __syncthreads();

        if (kt + STAGES - 1 < KITERS)
            load_stage(sbase, (kt + STAGES - 1) & (STAGES - 1),
                       A, B, bm, bn, kt + STAGES - 1, tid);

        const uint32_t st = sbase + (uint32_t)(kt & (STAGES - 1)) * STB;

        #pragma unroll
        for (int slice = 0; slice < 2; ++slice) {
            uint32_t af[4][4];
            #pragma unroll
            for (int mf = 0; mf < 4; ++mf) {
                const uint32_t off = sw_off(slice, wm * 64 + mf * 16 + rowA, gA);
                ldsm4(af[mf], st + off);
            }
            #pragma unroll
            for (int n16 = 0; n16 < 2; ++n16) {
                uint32_t bf[4];
                const uint32_t offB = sw_off(slice, wn * 32 + n16 * 16 + rowB, gB);
                ldsm4(bf, st + OPB + offB);
                #pragma unroll
                for (int mf = 0; mf < 4; ++mf)
                    #pragma unroll
                    for (int h = 0; h < 2; ++h)
                        mma_f16(acc[mf][n16 * 2 + h], af[mf],
                                bf[2 * h], bf[2 * h + 1]);
            }
        }
    }

    // epilogue: per-section gate transform, then fp16 store
    const int mode = bn >> 10;           // 0=hidden 1=gate 2=proj (BN=128 | 1024)
    #pragma unroll
    for (int mf = 0; mf < 4; ++mf) {
        const int row = bm + wm * 64 + mf * 16 + (lane >> 2);
        #pragma unroll
        for (int nf = 0; nf < 4; ++nf) {
            const float* c = acc[mf][nf];
            const int col = bn + wn * 32 + (nf >> 1) * 16 + (nf & 1) * 8 + (lane & 3) * 2;
            float t0 = gate_xform(c[0], mode), t1 = gate_xform(c[1], mode);
            float t2 = gate_xform(c[2], mode), t3 = gate_xform(c[3], mode);
            *(__half2*)(C + (size_t)row * N3H + col)       = __floats2half2_rn(t0, t1);
            *(__half2*)(C + (size_t)(row + 8) * N3H + col) = __floats2half2_rn(t2, t3);
        }
    }
}

// ---------------------------------------------------------------------------
// Fused prologue: transpose+convert W0 and W1, convert A -> fp16.
// ---------------------------------------------------------------------------
#define WT_BLOCKS 3072            // (3072/32) * (1024/32)
#define CA_BLOCKS 32768           // MROWS*HDIM/4/256

__global__ void __launch_bounds__(256)
prep_kernel(const float* __restrict__ W0, const float* __restrict__ W1,
            const float* __restrict__ h,
            __half* __restrict__ w0t, __half* __restrict__ w1t,
            __half* __restrict__ af)
{
    const int bi = blockIdx.x;
    if (bi < 2 * WT_BLOCKS) {
        __shared__ float tile[32][33];
        const float* W = (bi < WT_BLOCKS) ? W0 : W1;
        __half* o = (bi < WT_BLOCKS) ? w0t : w1t;
        const int lb = (bi < WT_BLOCKS) ? bi : bi - WT_BLOCKS;
        const int n0 = (lb % 96) * 32;
        const int k0 = (lb / 96) * 32;
        const int tx = threadIdx.x & 31, ty = threadIdx.x >> 5;
        #pragma unroll
        for (int r = ty; r < 32; r += 8)
            tile[r][tx] = W[(size_t)(k0 + r) * N3H + n0 + tx];
        __syncthreads();
        #pragma unroll
        for (int r = ty; r < 32; r += 8)
            o[(size_t)(n0 + r) * KSZ + k0 + tx] = __float2half_rn(tile[tx][r]);
    } else {
        const size_t i = (size_t)(bi - 2 * WT_BLOCKS) * 256 + threadIdx.x;
        float4 v = ((const float4*)h)[i];
        ((__half2*)af)[2 * i]     = __floats2half2_rn(v.x, v.y);
        ((__half2*)af)[2 * i + 1] = __floats2half2_rn(v.z, v.w);
    }
}

// ---------------------------------------------------------------------------
// Scan phase 1 (2 channels/thread): P = prod cf, S = chunk-local scan end.
// Pure fma + loads (transforms already applied in GEMM epilogue).
// ---------------------------------------------------------------------------
__global__ void __launch_bounds__(256)
scan_p1(const __half* __restrict__ z, float* __restrict__ cP, float* __restrict__ cS)
{
    const int idx = blockIdx.x * blockDim.x + threadIdx.x;   // B*NC*512
    const int cp2 = idx & 511;               // channel pair
    const int chunk = (idx >> 9) & (NC - 1);
    const int b = idx >> 14;
    const __half* zb = z + ((size_t)b * TLEN + (size_t)chunk * CL) * N3H + cp2 * 2;
    float P0 = 1.0f, S0 = 0.0f, P1 = 1.0f, S1 = 0.0f;
    #pragma unroll 8
    for (int t = 0; t < CL; ++t) {
        float2 gv = __half22float2(*(const __half2*)(zb + (size_t)t * N3H));
        float2 cf = __half22float2(*(const __half2*)(zb + (size_t)t * N3H + HDIM));
        S0 = fmaf(cf.x, S0, (1.0f - cf.x) * gv.x);  P0 *= cf.x;
        S1 = fmaf(cf.y, S1, (1.0f - cf.y) * gv.y);  P1 *= cf.y;
    }
    const size_t o = (((size_t)(b * NC + chunk)) << 10) + cp2 * 2;
    *(float2*)(cP + o) = make_float2(P0, P1);
    *(float2*)(cS + o) = make_float2(S0, S1);
}

// ---------------------------------------------------------------------------
// Scan phase 3 (2 channels/thread), with inline p2: each block composes its
// own carry from cP/cS (j < chunk), then replays with the highway gate.
// layer==0: h0 from fp32 hin32, write fp16 af. layer==1: h0 from fp16 af,
// write fp32 out.
// ---------------------------------------------------------------------------
__global__ void __launch_bounds__(256)
scan_p3(const __half* __restrict__ z, const float* __restrict__ hin32,
        const __half* __restrict__ hin16,
        const float* __restrict__ cP, const float* __restrict__ cS,
        float* __restrict__ out32, __half* __restrict__ oa16, int layer)
{
    const int idx = blockIdx.x * blockDim.x + threadIdx.x;   // B*NC*512
    const int cp2 = idx & 511;
    const int chunk = (idx >> 9) & (NC - 1);
    const int b = idx >> 14;
    const size_t row0 = (size_t)b * TLEN + (size_t)chunk * CL;
    const __half* zb = z + row0 * N3H + cp2 * 2;

    // inline carry compose (was scan_p2)
    float s0 = 0.0f, s1 = 0.0f;
    for (int j = 0; j < chunk; ++j) {
        const size_t o = (((size_t)(b * NC + j)) << 10) + cp2 * 2;
        float2 P = *(const float2*)(cP + o);
        float2 S = *(const float2*)(cS + o);
        s0 = fmaf(P.x, s0, S.x);
        s1 = fmaf(P.y, s1, S.y);
    }

    #pragma unroll 4
    for (int t = 0; t < CL; ++t) {
        float2 gv = __half22float2(*(const __half2*)(zb + (size_t)t * N3H));
        float2 cf = __half22float2(*(const __half2*)(zb + (size_t)t * N3H + HDIM));
        float2 gp = __half22float2(*(const __half2*)(zb + (size_t)t * N3H + 2 * HDIM));
        float2 h0;
        const size_t ho = (row0 + t) * HDIM + cp2 * 2;
        if (layer == 0) h0 = *(const float2*)(hin32 + ho);
        else            h0 = __half22float2(*(const __half2*)(hin16 + ho));

        s0 = fmaf(cf.x, s0, (1.0f - cf.x) * gv.x);
        s1 = fmaf(cf.y, s1, (1.0f - cf.y) * gv.y);

        float o0 = fmaf(gp.x, s0 - h0.x, h0.x);
        float o1 = fmaf(gp.y, s1 - h0.y, h0.y);

        if (layer == 0)
            *(__half2*)(oa16 + ho) = __floats2half2_rn(o0, o1);
        else
            *(float2*)(out32 + ho) = make_float2(o0, o1);
    }
}

// ---------------------------------------------------------------------------
extern "C" void kernel_launch(void* const* d_in, const int* in_sizes, int n_in,
                              void* d_out, int out_size)
{
    const float* h  = (const float*)d_in[0];
    const float* W0 = (const float*)d_in[1];
    const float* W1 = (const float*)d_in[2];
    float* out = (float*)d_out;

    float *cP, *cS;
    __half *zbuf, *af, *w0t, *w1t;
    cudaGetSymbolAddress((void**)&zbuf, g_z);
    cudaGetSymbolAddress((void**)&af, g_af);
    cudaGetSymbolAddress((void**)&w0t, g_w0);
    cudaGetSymbolAddress((void**)&w1t, g_w1);
    cudaGetSymbolAddress((void**)&cP, g_cP);
    cudaGetSymbolAddress((void**)&cS, g_cS);

    cudaFuncSetAttribute(gemm_f16,
                         cudaFuncAttributeMaxDynamicSharedMemorySize, SMEM_DYN);

    const dim3 ggrid(N3H / GM_BN, MROWS / GM_BM);        // (24, 256)
    const int p1_blocks = (BSZ * NC * HDIM / 2) / 256;   // 512

    prep_kernel<<<2 * WT_BLOCKS + CA_BLOCKS, 256>>>(W0, W1, h, w0t, w1t, af);

    // ---- layer 0 ----
    gemm_f16<<<ggrid, 256, SMEM_DYN>>>(af, w0t, zbuf);
    scan_p1<<<p1_blocks, 256>>>(zbuf, cP, cS);
    scan_p3<<<p1_blocks, 256>>>(zbuf, h, (const __half*)0, cP, cS,
                                (float*)0, af, 0);

    // ---- layer 1 ----
    gemm_f16<<<ggrid, 256, SMEM_DYN>>>(af, w1t, zbuf);
    scan_p1<<<p1_blocks, 256>>>(zbuf, cP, cS);
    scan_p3<<<p1_blocks, 256>>>(zbuf, (const float*)0, af, cP, cS,
                                out, (__half*)0, 1);
}